// round 11
// baseline (speedup 1.0000x reference)
#include <cuda_runtime.h>
#include <math.h>

#define NN 131072
#define EE 1048576
#define HH 256
#define WW 256

typedef unsigned long long ull;

// ---------------- scratch (device globals; no allocations) ----------------
__device__ __align__(16) float g_h0[NN * 64];
__device__ __align__(16) float g_hw[NN * 64];
__device__ __align__(16) float g_q[NN * 64];
__device__ __align__(16) float g_k[NN * 64];
__device__ __align__(16) float g_v[NN * 64];
__device__ __align__(16) float g_acc[NN * 64];   // gcn output (pre-bn1)
__device__ __align__(16) float g_acc2[NN * 64];  // skip projection
__device__ __align__(16) float g_dinv[NN];
__device__ __align__(16) float g_wT[9 * 32 * 64];
// CSR (by destination col)
__device__ __align__(16) int    g_cnt[NN];
__device__ __align__(16) int    g_off[NN + 1];
__device__ __align__(16) int    g_cur[NN];
__device__ __align__(16) int    g_bsum[512];
__device__ __align__(16) int    g_bbase[512];
__device__ __align__(16) float4 g_meta[EE];      // {src bits, ew0, ew1, dst bits}

__device__ __forceinline__ float eluf(float x) {
    return x > 0.f ? x : 0.1f * expm1f(x);
}
__device__ __forceinline__ void fma2(ull& acc, ull a, ull w) {
    asm("fma.rn.f32x2 %0, %1, %2, %0;" : "+l"(acc) : "l"(a), "l"(w));
}
__device__ __forceinline__ ull dup2(float a) {
    ull r; asm("mov.b64 %0, {%1, %1};" : "=l"(r) : "f"(a)); return r;
}
__device__ __forceinline__ float2 unpack2(ull v) {
    float2 r; asm("mov.b64 {%0, %1}, %2;" : "=f"(r.x), "=f"(r.y) : "l"(v)); return r;
}

// ---------------- CSR build chain ----------------
__global__ void k_init() {
    int i = blockIdx.x * blockDim.x + threadIdx.x;
    if (i < NN) g_cnt[i] = 0;
}
__global__ void k_cnt(const int* __restrict__ ei) {
    int e = blockIdx.x * blockDim.x + threadIdx.x;
    if (e < EE) atomicAdd(&g_cnt[ei[EE + e]], 1);
}
__global__ void k_scan1() {
    int b = blockIdx.x, t = threadIdx.x;
    int i = b * 256 + t;
    int v = g_cnt[i];
    int lane = t & 31, wid = t >> 5;
    int x = v;
#pragma unroll
    for (int o = 1; o < 32; o <<= 1) {
        int y = __shfl_up_sync(0xffffffffu, x, o);
        if (lane >= o) x += y;
    }
    __shared__ int wsum[8];
    if (lane == 31) wsum[wid] = x;
    __syncthreads();
    if (t < 8) {
        int w = wsum[t];
#pragma unroll
        for (int o = 1; o < 8; o <<= 1) {
            int y = __shfl_up_sync(0xffu, w, o);
            if (t >= o) w += y;
        }
        wsum[t] = w;
    }
    __syncthreads();
    int base = wid > 0 ? wsum[wid - 1] : 0;
    int incl = base + x;
    g_off[i] = incl - v;
    if (t == 255) g_bsum[b] = incl;
}
__global__ void k_scan2() {
    int t = threadIdx.x;
    int v = g_bsum[t];
    int lane = t & 31, wid = t >> 5;
    int x = v;
#pragma unroll
    for (int o = 1; o < 32; o <<= 1) {
        int y = __shfl_up_sync(0xffffffffu, x, o);
        if (lane >= o) x += y;
    }
    __shared__ int ws[16];
    if (lane == 31) ws[wid] = x;
    __syncthreads();
    if (t < 16) {
        int w = ws[t];
#pragma unroll
        for (int o = 1; o < 16; o <<= 1) {
            int y = __shfl_up_sync(0xffffu, w, o);
            if (t >= o) w += y;
        }
        ws[t] = w;
    }
    __syncthreads();
    int base = wid > 0 ? ws[wid - 1] : 0;
    g_bbase[t] = base + x - v;
}
__global__ void k_scan3() {
    int i = blockIdx.x * 256 + threadIdx.x;
    int v = g_off[i] + g_bbase[i >> 8];
    g_off[i] = v;
    g_cur[i] = v;
    if (i == 0) g_off[NN] = EE;
}
__global__ void k_fill(const int* __restrict__ ei, const float* __restrict__ ew) {
    int e = blockIdx.x * blockDim.x + threadIdx.x;
    if (e < EE) {
        int r = ei[e], c = ei[EE + e];
        float2 w = ((const float2*)ew)[e];
        int pos = atomicAdd(&g_cur[c], 1);
        g_meta[pos] = make_float4(__int_as_float(r), w.x, w.y, __int_as_float(c));
    }
}
__global__ void k_degdinv() {
    int i = blockIdx.x * blockDim.x + threadIdx.x;
    if (i < NN) {
        int beg = g_off[i], end = g_off[i + 1];
        float d = 2.0f;
        for (int p = beg; p < end; p++) d += g_meta[p].z;
        g_dinv[i] = rsqrtf(d);
    }
}
__global__ void k_wprep(const float* __restrict__ cw) {
    int i = blockIdx.x * blockDim.x + threadIdx.x;
    if (i < 18432) {
        int co = i & 63;
        int ci = (i >> 6) & 31;
        int k  = i >> 11;
        int ky = k / 3, kx = k - ky * 3;
        g_wT[i] = cw[((co * 32 + ci) * 3 + ky) * 3 + kx];
    }
}

// ---------------- conv 3x3 SAME + bn2 + elu -----------------------------------
// 128 threads; tile 64px x 64co; micro 4px x 8co. Double-buffered per-k weights.
__global__ void __launch_bounds__(128)
k_conv(const float* __restrict__ x,
       const float* __restrict__ bg, const float* __restrict__ bb,
       const float* __restrict__ bm, const float* __restrict__ bv) {
    __shared__ __align__(16) float ins[32 * 204];
    __shared__ __align__(16) float wsk[2][2048];

    int tid = threadIdx.x;
    int bid = blockIdx.x;
    int xt = bid & 3;
    int y  = (bid >> 2) & 255;
    int b  = bid >> 10;
    int x0 = xt * 64;

    for (int i = tid; i < 3 * 66 * 32; i += 128) {
        int ci = i & 31;
        int p  = i >> 5;
        int r  = p / 66;
        int px = p - r * 66;
        int yy = y + r - 1;
        int xx = x0 + px - 1;
        float val = 0.f;
        if (yy >= 0 && yy < HH && xx >= 0 && xx < WW)
            val = x[(((size_t)b * HH + yy) * WW + xx) * 32 + ci];
        ins[ci * 204 + r * 68 + px] = val;
    }
    {
        const float4* wsrc = (const float4*)g_wT;
        float4* wdst = (float4*)wsk[0];
#pragma unroll
        for (int i = 0; i < 4; i++) wdst[tid + i * 128] = wsrc[tid + i * 128];
    }
    __syncthreads();

    int tx = tid & 7, ty = tid >> 3;     // tx 0..7, ty 0..15
    int co0 = tx * 8, px0 = ty * 4;

    ull acc[4][4];
#pragma unroll
    for (int i = 0; i < 4; i++)
#pragma unroll
        for (int j = 0; j < 4; j++) acc[i][j] = 0ull;

#pragma unroll
    for (int k = 0; k < 9; k++) {
        int buf = k & 1;
        int ky = k / 3, kx = k - ky * 3;
        const float* ipk = ins + ky * 68 + px0 + kx;
        const float* wb  = wsk[buf] + co0;
#pragma unroll 4
        for (int ci = 0; ci < 32; ci++) {
            const float* ip = ipk + ci * 204;
            float a0 = ip[0], a1 = ip[1], a2 = ip[2], a3 = ip[3];
            ulonglong2 w01 = *(const ulonglong2*)(wb + ci * 64);
            ulonglong2 w23 = *(const ulonglong2*)(wb + ci * 64 + 4);
            ull d0 = dup2(a0), d1 = dup2(a1), d2 = dup2(a2), d3 = dup2(a3);
            fma2(acc[0][0], d0, w01.x); fma2(acc[0][1], d0, w01.y);
            fma2(acc[0][2], d0, w23.x); fma2(acc[0][3], d0, w23.y);
            fma2(acc[1][0], d1, w01.x); fma2(acc[1][1], d1, w01.y);
            fma2(acc[1][2], d1, w23.x); fma2(acc[1][3], d1, w23.y);
            fma2(acc[2][0], d2, w01.x); fma2(acc[2][1], d2, w01.y);
            fma2(acc[2][2], d2, w23.x); fma2(acc[2][3], d2, w23.y);
            fma2(acc[3][0], d3, w01.x); fma2(acc[3][1], d3, w01.y);
            fma2(acc[3][2], d3, w23.x); fma2(acc[3][3], d3, w23.y);
        }
        if (k < 8) {
            const float4* wsrc = (const float4*)(g_wT + (k + 1) * 2048);
            float4* wdst = (float4*)wsk[buf ^ 1];
#pragma unroll
            for (int i = 0; i < 4; i++) wdst[tid + i * 128] = wsrc[tid + i * 128];
        }
        __syncthreads();
    }

    float sc[8], mm[8], bbv[8];
#pragma unroll
    for (int j = 0; j < 8; j++) {
        int c = co0 + j;
        sc[j]  = __ldg(&bg[c]) * rsqrtf(__ldg(&bv[c]) + 1e-5f);
        mm[j]  = __ldg(&bm[c]);
        bbv[j] = __ldg(&bb[c]);
    }
    size_t pixbase = ((size_t)b * HH + y) * WW + x0 + px0;
#pragma unroll
    for (int i = 0; i < 4; i++) {
        float2 p0 = unpack2(acc[i][0]);
        float2 p1 = unpack2(acc[i][1]);
        float2 p2 = unpack2(acc[i][2]);
        float2 p3 = unpack2(acc[i][3]);
        float r0 = eluf((p0.x - mm[0]) * sc[0] + bbv[0]);
        float r1 = eluf((p0.y - mm[1]) * sc[1] + bbv[1]);
        float r2 = eluf((p1.x - mm[2]) * sc[2] + bbv[2]);
        float r3 = eluf((p1.y - mm[3]) * sc[3] + bbv[3]);
        float r4 = eluf((p2.x - mm[4]) * sc[4] + bbv[4]);
        float r5 = eluf((p2.y - mm[5]) * sc[5] + bbv[5]);
        float r6 = eluf((p3.x - mm[6]) * sc[6] + bbv[6]);
        float r7 = eluf((p3.y - mm[7]) * sc[7] + bbv[7]);
        float* op = g_h0 + (pixbase + i) * 64 + co0;
        *(float4*)op       = make_float4(r0, r1, r2, r3);
        *(float4*)(op + 4) = make_float4(r4, r5, r6, r7);
    }
}

// ---------------- gemm1: hw = h0 @ gcn_w.T -----------------------------------
__global__ void __launch_bounds__(256)
k_gemm1(const float* __restrict__ in, const float* __restrict__ Wm) {
    extern __shared__ float sm[];
    float* sA = sm;               // [256][65]
    float* sW = sm + 256 * 65;    // [64][68]

    int tid = threadIdx.x;
    size_t base = (size_t)blockIdx.x * 256;

    const float4* src = (const float4*)(in + base * 64);
#pragma unroll
    for (int i = 0; i < 16; i++) {
        int idx = tid + i * 256;
        int node = idx >> 4, c4 = idx & 15;
        float4 v = src[idx];
        float* dst = &sA[node * 65 + c4 * 4];
        dst[0] = v.x; dst[1] = v.y; dst[2] = v.z; dst[3] = v.w;
    }
    const float4* w4 = (const float4*)Wm;
#pragma unroll
    for (int i = 0; i < 4; i++) {
        int idx = tid + i * 256;
        int co = idx >> 4, c4 = idx & 15;
        float4 v = w4[idx];
        sW[(c4 * 4 + 0) * 68 + co] = v.x;
        sW[(c4 * 4 + 1) * 68 + co] = v.y;
        sW[(c4 * 4 + 2) * 68 + co] = v.z;
        sW[(c4 * 4 + 3) * 68 + co] = v.w;
    }
    __syncthreads();

    int tx = tid & 7, ty = tid >> 3;
    int co0 = tx * 8, n0 = ty * 8;

    ull acc[8][4];
#pragma unroll
    for (int i = 0; i < 8; i++)
#pragma unroll
        for (int j = 0; j < 4; j++) acc[i][j] = 0ull;

    for (int ci = 0; ci < 64; ci++) {
        ulonglong2 w01 = *(const ulonglong2*)&sW[ci * 68 + co0];
        ulonglong2 w23 = *(const ulonglong2*)&sW[ci * 68 + co0 + 4];
        const float* ap = &sA[n0 * 65 + ci];
#pragma unroll
        for (int i = 0; i < 8; i++) {
            ull a = dup2(ap[i * 65]);
            fma2(acc[i][0], a, w01.x); fma2(acc[i][1], a, w01.y);
            fma2(acc[i][2], a, w23.x); fma2(acc[i][3], a, w23.y);
        }
    }
#pragma unroll
    for (int i = 0; i < 8; i++) {
        size_t node = base + n0 + i;
        float2 p0 = unpack2(acc[i][0]), p1 = unpack2(acc[i][1]);
        float2 p2 = unpack2(acc[i][2]), p3 = unpack2(acc[i][3]);
        *(float4*)(g_hw + node * 64 + co0)     = make_float4(p0.x, p0.y, p1.x, p1.y);
        *(float4*)(g_hw + node * 64 + co0 + 4) = make_float4(p2.x, p2.y, p3.x, p3.y);
    }
}

// ---------------- gcn gather ----------------
__global__ void __launch_bounds__(256)
k_gcn_gather() {
    int tid = threadIdx.x;
    int l = tid & 15;
    int node = blockIdx.x * 16 + (tid >> 4);
    int beg = g_off[node], end = g_off[node + 1];
    float dinvc = g_dinv[node];
    float s = 2.0f * dinvc * dinvc;
    float4 h4 = ((const float4*)g_hw)[(size_t)node * 16 + l];
    float4 acc = make_float4(s * h4.x, s * h4.y, s * h4.z, s * h4.w);
    for (int p = beg; p < end; p++) {
        float4 m = g_meta[p];
        int r = __float_as_int(m.x);
        float coeff = g_dinv[r] * dinvc * m.z;
        float4 v4 = ((const float4*)g_hw)[(size_t)r * 16 + l];
        acc.x += coeff * v4.x; acc.y += coeff * v4.y;
        acc.z += coeff * v4.z; acc.w += coeff * v4.w;
    }
    ((float4*)g_acc)[(size_t)node * 16 + l] = acc;
}

// ---------------- gemm4: 128-node tile, double-buffered W, 3 CTA/SM ----------
__global__ void __launch_bounds__(256)
k_gemm4(const float* __restrict__ gb,
        const float* __restrict__ g1, const float* __restrict__ b1,
        const float* __restrict__ m1, const float* __restrict__ v1,
        const float* __restrict__ W0, const float* __restrict__ W1,
        const float* __restrict__ W2, const float* __restrict__ W3,
        const float* __restrict__ bb0, const float* __restrict__ bb1,
        const float* __restrict__ bb2, const float* __restrict__ bb3,
        float* __restrict__ O0, float* __restrict__ O1,
        float* __restrict__ O2, float* __restrict__ O3) {
    extern __shared__ float sm[];
    float* sA  = sm;                       // [128][65] = 8320
    float* sW2 = sm + 8320;                // [2][64*68] = 8704
    float* bs  = sm + 8320 + 8704;         // [4][64]
    float* pSc = bs + 256;
    float* pOf = pSc + 64;

    int tid = threadIdx.x;
    size_t base = (size_t)blockIdx.x * 128;
    const float* Wsrc[4] = {W0, W1, W2, W3};

    if (tid < 64) {
        float scv = __ldg(&g1[tid]) * rsqrtf(__ldg(&v1[tid]) + 1e-5f);
        pSc[tid] = scv;
        pOf[tid] = (__ldg(&gb[tid]) - __ldg(&m1[tid])) * scv + __ldg(&b1[tid]);
        bs[tid]       = __ldg(&bb0[tid]);
        bs[64 + tid]  = __ldg(&bb1[tid]);
        bs[128 + tid] = __ldg(&bb2[tid]);
        bs[192 + tid] = __ldg(&bb3[tid]);
    }
    __syncthreads();

    const float4* src = (const float4*)(g_acc + base * 64);
#pragma unroll
    for (int i = 0; i < 8; i++) {
        int idx = tid + i * 256;               // 0..2047
        int node = idx >> 4, c4 = idx & 15;
        int c = c4 * 4;
        float4 v = src[idx];
        float* dst = &sA[node * 65 + c];
        dst[0] = eluf(v.x * pSc[c]     + pOf[c]);
        dst[1] = eluf(v.y * pSc[c + 1] + pOf[c + 1]);
        dst[2] = eluf(v.z * pSc[c + 2] + pOf[c + 2]);
        dst[3] = eluf(v.w * pSc[c + 3] + pOf[c + 3]);
    }
    {
        const float4* w4 = (const float4*)W0;
        float* wb = sW2;
#pragma unroll
        for (int i = 0; i < 4; i++) {
            int idx = tid + i * 256;
            int co = idx >> 4, c4 = idx & 15;
            float4 v = w4[idx];
            wb[(c4 * 4 + 0) * 68 + co] = v.x;
            wb[(c4 * 4 + 1) * 68 + co] = v.y;
            wb[(c4 * 4 + 2) * 68 + co] = v.z;
            wb[(c4 * 4 + 3) * 68 + co] = v.w;
        }
    }
    __syncthreads();

    int tx = tid & 7, ty = tid >> 3;   // ty 0..31
    int co0 = tx * 8, n0 = ty * 4;
    float* Odst[4] = {O0, O1, O2, O3};

#pragma unroll
    for (int m = 0; m < 4; m++) {
        if (m < 3) {
            const float4* w4 = (const float4*)Wsrc[m + 1];
            float* wb = sW2 + ((m + 1) & 1) * 4352;
#pragma unroll
            for (int i = 0; i < 4; i++) {
                int idx = tid + i * 256;
                int co = idx >> 4, c4 = idx & 15;
                float4 v = w4[idx];
                wb[(c4 * 4 + 0) * 68 + co] = v.x;
                wb[(c4 * 4 + 1) * 68 + co] = v.y;
                wb[(c4 * 4 + 2) * 68 + co] = v.z;
                wb[(c4 * 4 + 3) * 68 + co] = v.w;
            }
        }
        const float* wb = sW2 + (m & 1) * 4352;
        ulonglong2 bi0 = *(const ulonglong2*)&bs[m * 64 + co0];
        ulonglong2 bi1 = *(const ulonglong2*)&bs[m * 64 + co0 + 4];
        ull acc[4][4];
#pragma unroll
        for (int i = 0; i < 4; i++) {
            acc[i][0] = bi0.x; acc[i][1] = bi0.y;
            acc[i][2] = bi1.x; acc[i][3] = bi1.y;
        }
        for (int ci = 0; ci < 64; ci++) {
            ulonglong2 w01 = *(const ulonglong2*)&wb[ci * 68 + co0];
            ulonglong2 w23 = *(const ulonglong2*)&wb[ci * 68 + co0 + 4];
            const float* ap = &sA[n0 * 65 + ci];
#pragma unroll
            for (int i = 0; i < 4; i++) {
                ull a = dup2(ap[i * 65]);
                fma2(acc[i][0], a, w01.x); fma2(acc[i][1], a, w01.y);
                fma2(acc[i][2], a, w23.x); fma2(acc[i][3], a, w23.y);
            }
        }
        float* out = Odst[m];
#pragma unroll
        for (int i = 0; i < 4; i++) {
            size_t node = base + n0 + i;
            float2 p0 = unpack2(acc[i][0]), p1 = unpack2(acc[i][1]);
            float2 p2 = unpack2(acc[i][2]), p3 = unpack2(acc[i][3]);
            *(float4*)(out + node * 64 + co0)     = make_float4(p0.x, p0.y, p1.x, p1.y);
            *(float4*)(out + node * 64 + co0 + 4) = make_float4(p2.x, p2.y, p3.x, p3.y);
        }
        __syncthreads();
    }
}

// ---------------- fused attention: single pass (R9 best) ---------------------
__global__ void __launch_bounds__(256)
k_attn(const float* __restrict__ we,
       const float* __restrict__ g1, const float* __restrict__ b1,
       const float* __restrict__ m1, const float* __restrict__ v1,
       const float* __restrict__ wl, const float* __restrict__ bl,
       float* __restrict__ out) {
    __shared__ float4 wesm4[32];
    int tid = threadIdx.x;
    if (tid < 32) wesm4[tid] = ((const float4*)we)[tid];
    __syncthreads();

    int l = tid & 15;
    int node = blockIdx.x * 16 + (tid >> 4);
    int beg = g_off[node], end = g_off[node + 1];
    unsigned mask = 0xFFFFu << (tid & 16);

    float4 q4 = ((const float4*)g_q)[(size_t)node * 16 + l];
    float4 wa = wesm4[l * 2];
    float4 wb = wesm4[l * 2 + 1];

    float qe0 = q4.x * wa.x + q4.y * wa.z + q4.z * wb.x + q4.w * wb.z;
    float qe1 = q4.x * wa.y + q4.y * wa.w + q4.z * wb.y + q4.w * wb.w;
    qe0 += __shfl_xor_sync(mask, qe0, 8); qe1 += __shfl_xor_sync(mask, qe1, 8);
    qe0 += __shfl_xor_sync(mask, qe0, 4); qe1 += __shfl_xor_sync(mask, qe1, 4);
    qe0 += __shfl_xor_sync(mask, qe0, 2); qe1 += __shfl_xor_sync(mask, qe1, 2);
    qe0 += __shfl_xor_sync(mask, qe0, 1); qe1 += __shfl_xor_sync(mask, qe1, 1);

    float d = 0.f;
    float4 acc = make_float4(0.f, 0.f, 0.f, 0.f);
    float ew0a = 0.f, ew1a = 0.f;
#pragma unroll 2
    for (int p = beg; p < end; p++) {
        float4 m = g_meta[p];
        int r = __float_as_int(m.x);
        float4 k4 = ((const float4*)g_k)[(size_t)r * 16 + l];
        float s = q4.x * k4.x + q4.y * k4.y + q4.z * k4.z + q4.w * k4.w;
        s += __shfl_xor_sync(mask, s, 8);
        s += __shfl_xor_sync(mask, s, 4);
        s += __shfl_xor_sync(mask, s, 2);
        s += __shfl_xor_sync(mask, s, 1);
        s = (s + qe0 * m.y + qe1 * m.z) * 0.125f;
        float f = expf(s);
        float4 v4 = ((const float4*)g_v)[(size_t)r * 16 + l];
        d += f;
        ew0a += f * m.y;
        ew1a += f * m.z;
        acc.x += f * v4.x; acc.y += f * v4.y;
        acc.z += f * v4.z; acc.w += f * v4.w;
    }
    float inv = d > 0.f ? 1.0f / d : 0.f;
    acc.x *= inv; acc.y *= inv; acc.z *= inv; acc.w *= inv;
    ew0a *= inv; ew1a *= inv;
    acc.x += wa.x * ew0a + wa.y * ew1a;
    acc.y += wa.z * ew0a + wa.w * ew1a;
    acc.z += wb.x * ew0a + wb.y * ew1a;
    acc.w += wb.z * ew0a + wb.w * ew1a;

    float4 skip = ((const float4*)g_acc2)[(size_t)node * 16 + l];
    int c0 = l * 4;
    float part = 0.f;
    float xv[4] = {acc.x + skip.x, acc.y + skip.y, acc.z + skip.z, acc.w + skip.w};
#pragma unroll
    for (int j = 0; j < 4; j++) {
        int c = c0 + j;
        float scv = __ldg(&g1[c]) * rsqrtf(__ldg(&v1[c]) + 1e-5f);
        float bnv = (xv[j] - __ldg(&m1[c])) * scv + __ldg(&b1[c]);
        part += bnv * __ldg(&wl[c]);
    }
    part += __shfl_xor_sync(mask, part, 8);
    part += __shfl_xor_sync(mask, part, 4);
    part += __shfl_xor_sync(mask, part, 2);
    part += __shfl_xor_sync(mask, part, 1);
    if (l == 0) out[node] = part + __ldg(&bl[0]);
}

// ---------------- host launcher (two-stream fork/join) ----------------------
extern "C" void kernel_launch(void* const* d_in, const int* in_sizes, int n_in,
                              void* d_out, int out_size) {
    (void)in_sizes; (void)n_in; (void)out_size;
    const float* x     = (const float*)d_in[0];
    const int*   ei    = (const int*)d_in[1];
    const float* ew    = (const float*)d_in[2];
    const float* cw    = (const float*)d_in[6];
    const float* bn2g  = (const float*)d_in[7];
    const float* bn2b  = (const float*)d_in[8];
    const float* bn2m  = (const float*)d_in[9];
    const float* bn2v  = (const float*)d_in[10];
    const float* gcnw  = (const float*)d_in[11];
    const float* gcnb  = (const float*)d_in[12];
    const float* bn1g  = (const float*)d_in[13];
    const float* bn1b  = (const float*)d_in[14];
    const float* bn1m  = (const float*)d_in[15];
    const float* bn1v  = (const float*)d_in[16];
    const float* wq    = (const float*)d_in[17];
    const float* bq    = (const float*)d_in[18];
    const float* wk    = (const float*)d_in[19];
    const float* bk    = (const float*)d_in[20];
    const float* wv    = (const float*)d_in[21];
    const float* bv    = (const float*)d_in[22];
    const float* we    = (const float*)d_in[23];
    const float* wsk   = (const float*)d_in[24];
    const float* bsk   = (const float*)d_in[25];
    const float* wl    = (const float*)d_in[26];
    const float* bl    = (const float*)d_in[27];

    float *p_h0, *p_q, *p_k, *p_v, *p_acc2;
    cudaGetSymbolAddress((void**)&p_h0,   g_h0);
    cudaGetSymbolAddress((void**)&p_q,    g_q);
    cudaGetSymbolAddress((void**)&p_k,    g_k);
    cudaGetSymbolAddress((void**)&p_v,    g_v);
    cudaGetSymbolAddress((void**)&p_acc2, g_acc2);

    const int gemm1_smem = (256 * 65 + 64 * 68) * 4;
    const int gemm4_smem = (8320 + 8704 + 256 + 128) * 4;

    static cudaStream_t s2 = nullptr;
    static cudaEvent_t evF = nullptr, evJ = nullptr;
    static bool attrSet = false;
    if (!attrSet) {
        cudaFuncSetAttribute(k_gemm1, cudaFuncAttributeMaxDynamicSharedMemorySize, gemm1_smem);
        cudaFuncSetAttribute(k_gemm4, cudaFuncAttributeMaxDynamicSharedMemorySize, gemm4_smem);
        cudaStreamCreateWithFlags(&s2, cudaStreamNonBlocking);
        cudaEventCreateWithFlags(&evF, cudaEventDisableTiming);
        cudaEventCreateWithFlags(&evJ, cudaEventDisableTiming);
        attrSet = true;
    }

    if (s2 && evF && evJ) {
        cudaEventRecord(evF, 0);
        cudaStreamWaitEvent(s2, evF, 0);
        k_init<<<NN / 256, 256, 0, s2>>>();
        k_cnt<<<EE / 256, 256, 0, s2>>>(ei);
        k_scan1<<<512, 256, 0, s2>>>();
        k_scan2<<<1, 512, 0, s2>>>();
        k_scan3<<<512, 256, 0, s2>>>();
        k_fill<<<EE / 256, 256, 0, s2>>>(ei, ew);
        k_degdinv<<<NN / 256, 256, 0, s2>>>();
        cudaEventRecord(evJ, s2);

        k_wprep<<<72, 256>>>(cw);
        k_conv<<<2048, 128>>>(x, bn2g, bn2b, bn2m, bn2v);
        k_gemm1<<<NN / 256, 256, gemm1_smem>>>(p_h0, gcnw);

        cudaStreamWaitEvent(0, evJ, 0);
    } else {
        k_init<<<NN / 256, 256>>>();
        k_cnt<<<EE / 256, 256>>>(ei);
        k_scan1<<<512, 256>>>();
        k_scan2<<<1, 512>>>();
        k_scan3<<<512, 256>>>();
        k_fill<<<EE / 256, 256>>>(ei, ew);
        k_degdinv<<<NN / 256, 256>>>();
        k_wprep<<<72, 256>>>(cw);
        k_conv<<<2048, 128>>>(x, bn2g, bn2b, bn2m, bn2v);
        k_gemm1<<<NN / 256, 256, gemm1_smem>>>(p_h0, gcnw);
    }

    k_gcn_gather<<<NN / 16, 256>>>();
    k_gemm4<<<NN / 128, 256, gemm4_smem>>>(gcnb, bn1g, bn1b, bn1m, bn1v,
                                           wq, wk, wv, wsk, bq, bk, bv, bsk,
                                           p_q, p_k, p_v, p_acc2);
    k_attn<<<NN / 16, 256>>>(we, bn1g, bn1b, bn1m, bn1v, wl, bl, (float*)d_out);
}

// round 12
// speedup vs baseline: 1.2001x; 1.2001x over previous
#include <cuda_runtime.h>
#include <cuda_bf16.h>
#include <math.h>

#define NN 131072
#define EE 1048576
#define HH 256
#define WW 256

typedef unsigned long long ull;

// ---------------- scratch (device globals; no allocations) ----------------
__device__ __align__(16) float g_h0[NN * 64];
__device__ __align__(16) float g_hw[NN * 64];
__device__ __align__(16) float g_q[NN * 64];
__device__ __align__(16) __nv_bfloat16 g_kh[NN * 64];   // k in bf16
__device__ __align__(16) __nv_bfloat16 g_vh[NN * 64];   // v in bf16
__device__ __align__(16) float g_acc[NN * 64];   // gcn output (pre-bn1)
__device__ __align__(16) float g_acc2[NN * 64];  // skip projection
__device__ __align__(16) float g_dinv[NN];
__device__ __align__(16) float g_wT[9 * 32 * 64];
// CSR (by destination col)
__device__ __align__(16) int    g_cnt[NN];
__device__ __align__(16) int    g_off[NN + 1];
__device__ __align__(16) int    g_cur[NN];
__device__ __align__(16) int    g_bsum[512];
__device__ __align__(16) int    g_bbase[512];
__device__ __align__(16) float4 g_meta[EE];      // {src bits, ew0, ew1, dst bits}

__device__ __forceinline__ float eluf(float x) {
    return x > 0.f ? x : 0.1f * expm1f(x);
}
__device__ __forceinline__ void fma2(ull& acc, ull a, ull w) {
    asm("fma.rn.f32x2 %0, %1, %2, %0;" : "+l"(acc) : "l"(a), "l"(w));
}
__device__ __forceinline__ ull dup2(float a) {
    ull r; asm("mov.b64 %0, {%1, %1};" : "=l"(r) : "f"(a)); return r;
}
__device__ __forceinline__ float2 unpack2(ull v) {
    float2 r; asm("mov.b64 {%0, %1}, %2;" : "=f"(r.x), "=f"(r.y) : "l"(v)); return r;
}

// ---------------- CSR build chain ----------------
__global__ void k_init() {
    int i = blockIdx.x * blockDim.x + threadIdx.x;
    if (i < NN) g_cnt[i] = 0;
}
__global__ void k_cnt(const int* __restrict__ ei) {
    int e = blockIdx.x * blockDim.x + threadIdx.x;
    if (e < EE) atomicAdd(&g_cnt[ei[EE + e]], 1);
}
__global__ void k_scan1() {
    int b = blockIdx.x, t = threadIdx.x;
    int i = b * 256 + t;
    int v = g_cnt[i];
    int lane = t & 31, wid = t >> 5;
    int x = v;
#pragma unroll
    for (int o = 1; o < 32; o <<= 1) {
        int y = __shfl_up_sync(0xffffffffu, x, o);
        if (lane >= o) x += y;
    }
    __shared__ int wsum[8];
    if (lane == 31) wsum[wid] = x;
    __syncthreads();
    if (t < 8) {
        int w = wsum[t];
#pragma unroll
        for (int o = 1; o < 8; o <<= 1) {
            int y = __shfl_up_sync(0xffu, w, o);
            if (t >= o) w += y;
        }
        wsum[t] = w;
    }
    __syncthreads();
    int base = wid > 0 ? wsum[wid - 1] : 0;
    int incl = base + x;
    g_off[i] = incl - v;
    if (t == 255) g_bsum[b] = incl;
}
__global__ void k_scan2() {
    int t = threadIdx.x;
    int v = g_bsum[t];
    int lane = t & 31, wid = t >> 5;
    int x = v;
#pragma unroll
    for (int o = 1; o < 32; o <<= 1) {
        int y = __shfl_up_sync(0xffffffffu, x, o);
        if (lane >= o) x += y;
    }
    __shared__ int ws[16];
    if (lane == 31) ws[wid] = x;
    __syncthreads();
    if (t < 16) {
        int w = ws[t];
#pragma unroll
        for (int o = 1; o < 16; o <<= 1) {
            int y = __shfl_up_sync(0xffffu, w, o);
            if (t >= o) w += y;
        }
        ws[t] = w;
    }
    __syncthreads();
    int base = wid > 0 ? ws[wid - 1] : 0;
    g_bbase[t] = base + x - v;
}
__global__ void k_scan3() {
    int i = blockIdx.x * 256 + threadIdx.x;
    int v = g_off[i] + g_bbase[i >> 8];
    g_off[i] = v;
    g_cur[i] = v;
    if (i == 0) g_off[NN] = EE;
}
__global__ void k_fill(const int* __restrict__ ei, const float* __restrict__ ew) {
    int e = blockIdx.x * blockDim.x + threadIdx.x;
    if (e < EE) {
        int r = ei[e], c = ei[EE + e];
        float2 w = ((const float2*)ew)[e];
        int pos = atomicAdd(&g_cur[c], 1);
        g_meta[pos] = make_float4(__int_as_float(r), w.x, w.y, __int_as_float(c));
    }
}
__global__ void k_degdinv() {
    int i = blockIdx.x * blockDim.x + threadIdx.x;
    if (i < NN) {
        int beg = g_off[i], end = g_off[i + 1];
        float d = 2.0f;
        for (int p = beg; p < end; p++) d += g_meta[p].z;
        g_dinv[i] = rsqrtf(d);
    }
}
__global__ void k_wprep(const float* __restrict__ cw) {
    int i = blockIdx.x * blockDim.x + threadIdx.x;
    if (i < 18432) {
        int co = i & 63;
        int ci = (i >> 6) & 31;
        int k  = i >> 11;
        int ky = k / 3, kx = k - ky * 3;
        g_wT[i] = cw[((co * 32 + ci) * 3 + ky) * 3 + kx];
    }
}

// ---------------- conv 3x3 SAME + bn2 + elu (R9 version) ----------------------
__global__ void __launch_bounds__(256)
k_conv(const float* __restrict__ x,
       const float* __restrict__ bg, const float* __restrict__ bb,
       const float* __restrict__ bm, const float* __restrict__ bv) {
    __shared__ __align__(16) float ins[32 * 204];
    __shared__ __align__(16) float wsk[2][2048];

    int tid = threadIdx.x;
    int bid = blockIdx.x;
    int xt = bid & 3;
    int y  = (bid >> 2) & 255;
    int b  = bid >> 10;
    int x0 = xt * 64;

    for (int i = tid; i < 3 * 66 * 32; i += 256) {
        int ci = i & 31;
        int p  = i >> 5;
        int r  = p / 66;
        int px = p - r * 66;
        int yy = y + r - 1;
        int xx = x0 + px - 1;
        float val = 0.f;
        if (yy >= 0 && yy < HH && xx >= 0 && xx < WW)
            val = x[(((size_t)b * HH + yy) * WW + xx) * 32 + ci];
        ins[ci * 204 + r * 68 + px] = val;
    }
    {
        const float4* wsrc = (const float4*)g_wT;
        float4* wdst = (float4*)wsk[0];
#pragma unroll
        for (int i = 0; i < 2; i++) wdst[tid + i * 256] = wsrc[tid + i * 256];
    }
    __syncthreads();

    int tx = tid & 15, ty = tid >> 4;
    int co0 = tx * 4, px0 = ty * 4;

    ull acc[4][2];
#pragma unroll
    for (int i = 0; i < 4; i++) { acc[i][0] = 0ull; acc[i][1] = 0ull; }

#pragma unroll
    for (int k = 0; k < 9; k++) {
        int buf = k & 1;
        int ky = k / 3, kx = k - ky * 3;
        const float* ipk = ins + ky * 68 + px0 + kx;
        const float* wb  = wsk[buf] + co0;
#pragma unroll 4
        for (int ci = 0; ci < 32; ci++) {
            const float* ip = ipk + ci * 204;
            float a0 = ip[0], a1 = ip[1], a2 = ip[2], a3 = ip[3];
            ulonglong2 w = *(const ulonglong2*)(wb + ci * 64);
            ull d0 = dup2(a0), d1 = dup2(a1), d2 = dup2(a2), d3 = dup2(a3);
            fma2(acc[0][0], d0, w.x); fma2(acc[0][1], d0, w.y);
            fma2(acc[1][0], d1, w.x); fma2(acc[1][1], d1, w.y);
            fma2(acc[2][0], d2, w.x); fma2(acc[2][1], d2, w.y);
            fma2(acc[3][0], d3, w.x); fma2(acc[3][1], d3, w.y);
        }
        if (k < 8) {
            const float4* wsrc = (const float4*)(g_wT + (k + 1) * 2048);
            float4* wdst = (float4*)wsk[buf ^ 1];
#pragma unroll
            for (int i = 0; i < 2; i++) wdst[tid + i * 256] = wsrc[tid + i * 256];
        }
        __syncthreads();
    }

    float sc[4], mm[4], bbv[4];
#pragma unroll
    for (int j = 0; j < 4; j++) {
        int c = co0 + j;
        sc[j]  = __ldg(&bg[c]) * rsqrtf(__ldg(&bv[c]) + 1e-5f);
        mm[j]  = __ldg(&bm[c]);
        bbv[j] = __ldg(&bb[c]);
    }
    size_t pixbase = ((size_t)b * HH + y) * WW + x0 + px0;
#pragma unroll
    for (int i = 0; i < 4; i++) {
        float2 p0 = unpack2(acc[i][0]);
        float2 p1 = unpack2(acc[i][1]);
        float r0 = eluf((p0.x - mm[0]) * sc[0] + bbv[0]);
        float r1 = eluf((p0.y - mm[1]) * sc[1] + bbv[1]);
        float r2 = eluf((p1.x - mm[2]) * sc[2] + bbv[2]);
        float r3 = eluf((p1.y - mm[3]) * sc[3] + bbv[3]);
        *(float4*)(g_h0 + (pixbase + i) * 64 + co0) = make_float4(r0, r1, r2, r3);
    }
}

// ---------------- gemm1: hw = h0 @ gcn_w.T -----------------------------------
__global__ void __launch_bounds__(256)
k_gemm1(const float* __restrict__ in, const float* __restrict__ Wm) {
    extern __shared__ float sm[];
    float* sA = sm;               // [256][65]
    float* sW = sm + 256 * 65;    // [64][68]

    int tid = threadIdx.x;
    size_t base = (size_t)blockIdx.x * 256;

    const float4* src = (const float4*)(in + base * 64);
#pragma unroll
    for (int i = 0; i < 16; i++) {
        int idx = tid + i * 256;
        int node = idx >> 4, c4 = idx & 15;
        float4 v = src[idx];
        float* dst = &sA[node * 65 + c4 * 4];
        dst[0] = v.x; dst[1] = v.y; dst[2] = v.z; dst[3] = v.w;
    }
    const float4* w4 = (const float4*)Wm;
#pragma unroll
    for (int i = 0; i < 4; i++) {
        int idx = tid + i * 256;
        int co = idx >> 4, c4 = idx & 15;
        float4 v = w4[idx];
        sW[(c4 * 4 + 0) * 68 + co] = v.x;
        sW[(c4 * 4 + 1) * 68 + co] = v.y;
        sW[(c4 * 4 + 2) * 68 + co] = v.z;
        sW[(c4 * 4 + 3) * 68 + co] = v.w;
    }
    __syncthreads();

    int tx = tid & 7, ty = tid >> 3;
    int co0 = tx * 8, n0 = ty * 8;

    ull acc[8][4];
#pragma unroll
    for (int i = 0; i < 8; i++)
#pragma unroll
        for (int j = 0; j < 4; j++) acc[i][j] = 0ull;

    for (int ci = 0; ci < 64; ci++) {
        ulonglong2 w01 = *(const ulonglong2*)&sW[ci * 68 + co0];
        ulonglong2 w23 = *(const ulonglong2*)&sW[ci * 68 + co0 + 4];
        const float* ap = &sA[n0 * 65 + ci];
#pragma unroll
        for (int i = 0; i < 8; i++) {
            ull a = dup2(ap[i * 65]);
            fma2(acc[i][0], a, w01.x); fma2(acc[i][1], a, w01.y);
            fma2(acc[i][2], a, w23.x); fma2(acc[i][3], a, w23.y);
        }
    }
#pragma unroll
    for (int i = 0; i < 8; i++) {
        size_t node = base + n0 + i;
        float2 p0 = unpack2(acc[i][0]), p1 = unpack2(acc[i][1]);
        float2 p2 = unpack2(acc[i][2]), p3 = unpack2(acc[i][3]);
        *(float4*)(g_hw + node * 64 + co0)     = make_float4(p0.x, p0.y, p1.x, p1.y);
        *(float4*)(g_hw + node * 64 + co0 + 4) = make_float4(p2.x, p2.y, p3.x, p3.y);
    }
}

// ---------------- gcn gather ----------------
__global__ void __launch_bounds__(256)
k_gcn_gather() {
    int tid = threadIdx.x;
    int l = tid & 15;
    int node = blockIdx.x * 16 + (tid >> 4);
    int beg = g_off[node], end = g_off[node + 1];
    float dinvc = g_dinv[node];
    float s = 2.0f * dinvc * dinvc;
    float4 h4 = ((const float4*)g_hw)[(size_t)node * 16 + l];
    float4 acc = make_float4(s * h4.x, s * h4.y, s * h4.z, s * h4.w);
    for (int p = beg; p < end; p++) {
        float4 m = g_meta[p];
        int r = __float_as_int(m.x);
        float coeff = g_dinv[r] * dinvc * m.z;
        float4 v4 = ((const float4*)g_hw)[(size_t)r * 16 + l];
        acc.x += coeff * v4.x; acc.y += coeff * v4.y;
        acc.z += coeff * v4.z; acc.w += coeff * v4.w;
    }
    ((float4*)g_acc)[(size_t)node * 16 + l] = acc;
}

// ---------------- gemm4 (R9 tile; k/v written as bf16) -----------------------
__global__ void __launch_bounds__(256)
k_gemm4(const float* __restrict__ gb,
        const float* __restrict__ g1, const float* __restrict__ b1,
        const float* __restrict__ m1, const float* __restrict__ v1,
        const float* __restrict__ W0, const float* __restrict__ W1,
        const float* __restrict__ W2, const float* __restrict__ W3,
        const float* __restrict__ bb0, const float* __restrict__ bb1,
        const float* __restrict__ bb2, const float* __restrict__ bb3) {
    extern __shared__ float sm[];
    float* sA  = sm;                       // [256][65]
    float* sW2 = sm + 16640;               // [2][64*68]
    float* bs  = sm + 16640 + 8704;        // [4][64]
    float* pSc = bs + 256;
    float* pOf = pSc + 64;

    int tid = threadIdx.x;
    size_t base = (size_t)blockIdx.x * 256;
    const float* Wsrc[4] = {W0, W1, W2, W3};

    if (tid < 64) {
        float scv = __ldg(&g1[tid]) * rsqrtf(__ldg(&v1[tid]) + 1e-5f);
        pSc[tid] = scv;
        pOf[tid] = (__ldg(&gb[tid]) - __ldg(&m1[tid])) * scv + __ldg(&b1[tid]);
        bs[tid]       = __ldg(&bb0[tid]);
        bs[64 + tid]  = __ldg(&bb1[tid]);
        bs[128 + tid] = __ldg(&bb2[tid]);
        bs[192 + tid] = __ldg(&bb3[tid]);
    }
    __syncthreads();

    const float4* src = (const float4*)(g_acc + base * 64);
#pragma unroll
    for (int i = 0; i < 16; i++) {
        int idx = tid + i * 256;
        int node = idx >> 4, c4 = idx & 15;
        int c = c4 * 4;
        float4 v = src[idx];
        float* dst = &sA[node * 65 + c];
        dst[0] = eluf(v.x * pSc[c]     + pOf[c]);
        dst[1] = eluf(v.y * pSc[c + 1] + pOf[c + 1]);
        dst[2] = eluf(v.z * pSc[c + 2] + pOf[c + 2]);
        dst[3] = eluf(v.w * pSc[c + 3] + pOf[c + 3]);
    }
    {
        const float4* w4 = (const float4*)W0;
        float* wb = sW2;
#pragma unroll
        for (int i = 0; i < 4; i++) {
            int idx = tid + i * 256;
            int co = idx >> 4, c4 = idx & 15;
            float4 v = w4[idx];
            wb[(c4 * 4 + 0) * 68 + co] = v.x;
            wb[(c4 * 4 + 1) * 68 + co] = v.y;
            wb[(c4 * 4 + 2) * 68 + co] = v.z;
            wb[(c4 * 4 + 3) * 68 + co] = v.w;
        }
    }
    __syncthreads();

    int tx = tid & 7, ty = tid >> 3;
    int co0 = tx * 8, n0 = ty * 8;

#pragma unroll
    for (int m = 0; m < 4; m++) {
        if (m < 3) {
            const float4* w4 = (const float4*)Wsrc[m + 1];
            float* wb = sW2 + ((m + 1) & 1) * 4352;
#pragma unroll
            for (int i = 0; i < 4; i++) {
                int idx = tid + i * 256;
                int co = idx >> 4, c4 = idx & 15;
                float4 v = w4[idx];
                wb[(c4 * 4 + 0) * 68 + co] = v.x;
                wb[(c4 * 4 + 1) * 68 + co] = v.y;
                wb[(c4 * 4 + 2) * 68 + co] = v.z;
                wb[(c4 * 4 + 3) * 68 + co] = v.w;
            }
        }
        const float* wb = sW2 + (m & 1) * 4352;
        ulonglong2 bi0 = *(const ulonglong2*)&bs[m * 64 + co0];
        ulonglong2 bi1 = *(const ulonglong2*)&bs[m * 64 + co0 + 4];
        ull acc[8][4];
#pragma unroll
        for (int i = 0; i < 8; i++) {
            acc[i][0] = bi0.x; acc[i][1] = bi0.y;
            acc[i][2] = bi1.x; acc[i][3] = bi1.y;
        }
        for (int ci = 0; ci < 64; ci++) {
            ulonglong2 w01 = *(const ulonglong2*)&wb[ci * 68 + co0];
            ulonglong2 w23 = *(const ulonglong2*)&wb[ci * 68 + co0 + 4];
            const float* ap = &sA[n0 * 65 + ci];
#pragma unroll
            for (int i = 0; i < 8; i++) {
                ull a = dup2(ap[i * 65]);
                fma2(acc[i][0], a, w01.x); fma2(acc[i][1], a, w01.y);
                fma2(acc[i][2], a, w23.x); fma2(acc[i][3], a, w23.y);
            }
        }
        if (m == 0 || m == 3) {
            float* out = (m == 0) ? g_q : g_acc2;
#pragma unroll
            for (int i = 0; i < 8; i++) {
                size_t node = base + n0 + i;
                float2 p0 = unpack2(acc[i][0]), p1 = unpack2(acc[i][1]);
                float2 p2 = unpack2(acc[i][2]), p3 = unpack2(acc[i][3]);
                *(float4*)(out + node * 64 + co0)     = make_float4(p0.x, p0.y, p1.x, p1.y);
                *(float4*)(out + node * 64 + co0 + 4) = make_float4(p2.x, p2.y, p3.x, p3.y);
            }
        } else {
            __nv_bfloat16* out = (m == 1) ? g_kh : g_vh;
#pragma unroll
            for (int i = 0; i < 8; i++) {
                size_t node = base + n0 + i;
                uint4 o;
                float2 p0 = unpack2(acc[i][0]);
                float2 p1 = unpack2(acc[i][1]);
                float2 p2 = unpack2(acc[i][2]);
                float2 p3 = unpack2(acc[i][3]);
                __nv_bfloat162 b0 = __float22bfloat162_rn(p0);
                __nv_bfloat162 b1 = __float22bfloat162_rn(p1);
                __nv_bfloat162 b2 = __float22bfloat162_rn(p2);
                __nv_bfloat162 b3 = __float22bfloat162_rn(p3);
                o.x = *(unsigned*)&b0; o.y = *(unsigned*)&b1;
                o.z = *(unsigned*)&b2; o.w = *(unsigned*)&b3;
                *(uint4*)(out + node * 64 + co0) = o;
            }
        }
        __syncthreads();
    }
}

// ---------------- fused attention: single pass, bf16 k/v gathers -------------
__global__ void __launch_bounds__(256)
k_attn(const float* __restrict__ we,
       const float* __restrict__ g1, const float* __restrict__ b1,
       const float* __restrict__ m1, const float* __restrict__ v1,
       const float* __restrict__ wl, const float* __restrict__ bl,
       float* __restrict__ out) {
    __shared__ float4 wesm4[32];
    int tid = threadIdx.x;
    if (tid < 32) wesm4[tid] = ((const float4*)we)[tid];
    __syncthreads();

    int l = tid & 15;
    int node = blockIdx.x * 16 + (tid >> 4);
    int beg = g_off[node], end = g_off[node + 1];
    unsigned mask = 0xFFFFu << (tid & 16);

    float4 q4 = ((const float4*)g_q)[(size_t)node * 16 + l];
    float4 wa = wesm4[l * 2];
    float4 wb = wesm4[l * 2 + 1];

    float qe0 = q4.x * wa.x + q4.y * wa.z + q4.z * wb.x + q4.w * wb.z;
    float qe1 = q4.x * wa.y + q4.y * wa.w + q4.z * wb.y + q4.w * wb.w;
    qe0 += __shfl_xor_sync(mask, qe0, 8); qe1 += __shfl_xor_sync(mask, qe1, 8);
    qe0 += __shfl_xor_sync(mask, qe0, 4); qe1 += __shfl_xor_sync(mask, qe1, 4);
    qe0 += __shfl_xor_sync(mask, qe0, 2); qe1 += __shfl_xor_sync(mask, qe1, 2);
    qe0 += __shfl_xor_sync(mask, qe0, 1); qe1 += __shfl_xor_sync(mask, qe1, 1);

    float d = 0.f;
    float4 acc = make_float4(0.f, 0.f, 0.f, 0.f);
    float ew0a = 0.f, ew1a = 0.f;
#pragma unroll 2
    for (int p = beg; p < end; p++) {
        float4 m = g_meta[p];
        int r = __float_as_int(m.x);
        uint2 kk = ((const uint2*)g_kh)[(size_t)r * 16 + l];
        float2 k0 = __bfloat1622float2(*(__nv_bfloat162*)&kk.x);
        float2 k1 = __bfloat1622float2(*(__nv_bfloat162*)&kk.y);
        float s = q4.x * k0.x + q4.y * k0.y + q4.z * k1.x + q4.w * k1.y;
        s += __shfl_xor_sync(mask, s, 8);
        s += __shfl_xor_sync(mask, s, 4);
        s += __shfl_xor_sync(mask, s, 2);
        s += __shfl_xor_sync(mask, s, 1);
        s = (s + qe0 * m.y + qe1 * m.z) * 0.125f;
        float f = expf(s);
        uint2 vv = ((const uint2*)g_vh)[(size_t)r * 16 + l];
        float2 v0 = __bfloat1622float2(*(__nv_bfloat162*)&vv.x);
        float2 v1 = __bfloat1622float2(*(__nv_bfloat162*)&vv.y);
        d += f;
        ew0a += f * m.y;
        ew1a += f * m.z;
        acc.x += f * v0.x; acc.y += f * v0.y;
        acc.z += f * v1.x; acc.w += f * v1.y;
    }
    float inv = d > 0.f ? 1.0f / d : 0.f;
    acc.x *= inv; acc.y *= inv; acc.z *= inv; acc.w *= inv;
    ew0a *= inv; ew1a *= inv;
    acc.x += wa.x * ew0a + wa.y * ew1a;
    acc.y += wa.z * ew0a + wa.w * ew1a;
    acc.z += wb.x * ew0a + wb.y * ew1a;
    acc.w += wb.z * ew0a + wb.w * ew1a;

    float4 skip = ((const float4*)g_acc2)[(size_t)node * 16 + l];
    int c0 = l * 4;
    float part = 0.f;
    float xv[4] = {acc.x + skip.x, acc.y + skip.y, acc.z + skip.z, acc.w + skip.w};
#pragma unroll
    for (int j = 0; j < 4; j++) {
        int c = c0 + j;
        float scv = __ldg(&g1[c]) * rsqrtf(__ldg(&v1[c]) + 1e-5f);
        float bnv = (xv[j] - __ldg(&m1[c])) * scv + __ldg(&b1[c]);
        part += bnv * __ldg(&wl[c]);
    }
    part += __shfl_xor_sync(mask, part, 8);
    part += __shfl_xor_sync(mask, part, 4);
    part += __shfl_xor_sync(mask, part, 2);
    part += __shfl_xor_sync(mask, part, 1);
    if (l == 0) out[node] = part + __ldg(&bl[0]);
}

// ---------------- host launcher (two-stream fork/join) ----------------------
extern "C" void kernel_launch(void* const* d_in, const int* in_sizes, int n_in,
                              void* d_out, int out_size) {
    (void)in_sizes; (void)n_in; (void)out_size;
    const float* x     = (const float*)d_in[0];
    const int*   ei    = (const int*)d_in[1];
    const float* ew    = (const float*)d_in[2];
    const float* cw    = (const float*)d_in[6];
    const float* bn2g  = (const float*)d_in[7];
    const float* bn2b  = (const float*)d_in[8];
    const float* bn2m  = (const float*)d_in[9];
    const float* bn2v  = (const float*)d_in[10];
    const float* gcnw  = (const float*)d_in[11];
    const float* gcnb  = (const float*)d_in[12];
    const float* bn1g  = (const float*)d_in[13];
    const float* bn1b  = (const float*)d_in[14];
    const float* bn1m  = (const float*)d_in[15];
    const float* bn1v  = (const float*)d_in[16];
    const float* wq    = (const float*)d_in[17];
    const float* bq    = (const float*)d_in[18];
    const float* wk    = (const float*)d_in[19];
    const float* bk    = (const float*)d_in[20];
    const float* wv    = (const float*)d_in[21];
    const float* bv    = (const float*)d_in[22];
    const float* we    = (const float*)d_in[23];
    const float* wsk   = (const float*)d_in[24];
    const float* bsk   = (const float*)d_in[25];
    const float* wl    = (const float*)d_in[26];
    const float* bl    = (const float*)d_in[27];

    float* p_h0;
    cudaGetSymbolAddress((void**)&p_h0, g_h0);

    const int gemm1_smem = (256 * 65 + 64 * 68) * 4;
    const int gemm4_smem = (16640 + 8704 + 256 + 128) * 4;

    static cudaStream_t s2 = nullptr;
    static cudaEvent_t evF = nullptr, evJ = nullptr;
    static bool attrSet = false;
    if (!attrSet) {
        cudaFuncSetAttribute(k_gemm1, cudaFuncAttributeMaxDynamicSharedMemorySize, gemm1_smem);
        cudaFuncSetAttribute(k_gemm4, cudaFuncAttributeMaxDynamicSharedMemorySize, gemm4_smem);
        cudaStreamCreateWithFlags(&s2, cudaStreamNonBlocking);
        cudaEventCreateWithFlags(&evF, cudaEventDisableTiming);
        cudaEventCreateWithFlags(&evJ, cudaEventDisableTiming);
        attrSet = true;
    }

    if (s2 && evF && evJ) {
        cudaEventRecord(evF, 0);
        cudaStreamWaitEvent(s2, evF, 0);
        k_init<<<NN / 256, 256, 0, s2>>>();
        k_cnt<<<EE / 256, 256, 0, s2>>>(ei);
        k_scan1<<<512, 256, 0, s2>>>();
        k_scan2<<<1, 512, 0, s2>>>();
        k_scan3<<<512, 256, 0, s2>>>();
        k_fill<<<EE / 256, 256, 0, s2>>>(ei, ew);
        k_degdinv<<<NN / 256, 256, 0, s2>>>();
        cudaEventRecord(evJ, s2);

        k_wprep<<<72, 256>>>(cw);
        k_conv<<<2048, 256>>>(x, bn2g, bn2b, bn2m, bn2v);
        k_gemm1<<<NN / 256, 256, gemm1_smem>>>(p_h0, gcnw);

        cudaStreamWaitEvent(0, evJ, 0);
    } else {
        k_init<<<NN / 256, 256>>>();
        k_cnt<<<EE / 256, 256>>>(ei);
        k_scan1<<<512, 256>>>();
        k_scan2<<<1, 512>>>();
        k_scan3<<<512, 256>>>();
        k_fill<<<EE / 256, 256>>>(ei, ew);
        k_degdinv<<<NN / 256, 256>>>();
        k_wprep<<<72, 256>>>(cw);
        k_conv<<<2048, 256>>>(x, bn2g, bn2b, bn2m, bn2v);
        k_gemm1<<<NN / 256, 256, gemm1_smem>>>(p_h0, gcnw);
    }

    k_gcn_gather<<<NN / 16, 256>>>();
    k_gemm4<<<NN / 256, 256, gemm4_smem>>>(gcnb, bn1g, bn1b, bn1m, bn1v,
                                           wq, wk, wv, wsk, bq, bk, bv, bsk);
    k_attn<<<NN / 16, 256>>>(we, bn1g, bn1b, bn1m, bn1v, wl, bl, (float*)d_out);
}

// round 13
// speedup vs baseline: 1.2210x; 1.0174x over previous
#include <cuda_runtime.h>
#include <cuda_fp16.h>
#include <math.h>

#define NN 131072
#define EE 1048576
#define HH 256
#define WW 256

typedef unsigned long long ull;

// ---------------- scratch (device globals; no allocations) ----------------
__device__ __align__(16) float g_h0[NN * 64];
__device__ __align__(16) __half g_hw[NN * 64];          // hw in fp16 (gather-only)
__device__ __align__(16) float g_q[NN * 64];
__device__ __align__(16) __half g_kh[NN * 64];          // k in fp16
__device__ __align__(16) __half g_vh[NN * 64];          // v in fp16
__device__ __align__(16) float g_acc[NN * 64];   // gcn output (pre-bn1)
__device__ __align__(16) float g_acc2[NN * 64];  // skip projection
__device__ __align__(16) float g_dinv[NN];
__device__ __align__(16) float g_wT[9 * 32 * 64];
// CSR (by destination col)
__device__ __align__(16) int    g_cnt[NN];
__device__ __align__(16) int    g_off[NN + 1];
__device__ __align__(16) int    g_cur[NN];
__device__ __align__(16) int    g_bsum[512];
__device__ __align__(16) int    g_bbase[512];
__device__ __align__(16) float4 g_meta[EE];      // {src bits, ew0, ew1, dst bits}

__device__ __forceinline__ float eluf(float x) {
    return x > 0.f ? x : 0.1f * expm1f(x);
}
__device__ __forceinline__ void fma2(ull& acc, ull a, ull w) {
    asm("fma.rn.f32x2 %0, %1, %2, %0;" : "+l"(acc) : "l"(a), "l"(w));
}
__device__ __forceinline__ ull dup2(float a) {
    ull r; asm("mov.b64 %0, {%1, %1};" : "=l"(r) : "f"(a)); return r;
}
__device__ __forceinline__ float2 unpack2(ull v) {
    float2 r; asm("mov.b64 {%0, %1}, %2;" : "=f"(r.x), "=f"(r.y) : "l"(v)); return r;
}

// ---------------- CSR build chain ----------------
__global__ void k_init() {
    int i = blockIdx.x * blockDim.x + threadIdx.x;
    if (i < NN) g_cnt[i] = 0;
}
__global__ void k_cnt(const int* __restrict__ ei) {
    int e = blockIdx.x * blockDim.x + threadIdx.x;
    if (e < EE) atomicAdd(&g_cnt[ei[EE + e]], 1);
}
__global__ void k_scan1() {
    int b = blockIdx.x, t = threadIdx.x;
    int i = b * 256 + t;
    int v = g_cnt[i];
    int lane = t & 31, wid = t >> 5;
    int x = v;
#pragma unroll
    for (int o = 1; o < 32; o <<= 1) {
        int y = __shfl_up_sync(0xffffffffu, x, o);
        if (lane >= o) x += y;
    }
    __shared__ int wsum[8];
    if (lane == 31) wsum[wid] = x;
    __syncthreads();
    if (t < 8) {
        int w = wsum[t];
#pragma unroll
        for (int o = 1; o < 8; o <<= 1) {
            int y = __shfl_up_sync(0xffu, w, o);
            if (t >= o) w += y;
        }
        wsum[t] = w;
    }
    __syncthreads();
    int base = wid > 0 ? wsum[wid - 1] : 0;
    int incl = base + x;
    g_off[i] = incl - v;
    if (t == 255) g_bsum[b] = incl;
}
__global__ void k_scan2() {
    int t = threadIdx.x;
    int v = g_bsum[t];
    int lane = t & 31, wid = t >> 5;
    int x = v;
#pragma unroll
    for (int o = 1; o < 32; o <<= 1) {
        int y = __shfl_up_sync(0xffffffffu, x, o);
        if (lane >= o) x += y;
    }
    __shared__ int ws[16];
    if (lane == 31) ws[wid] = x;
    __syncthreads();
    if (t < 16) {
        int w = ws[t];
#pragma unroll
        for (int o = 1; o < 16; o <<= 1) {
            int y = __shfl_up_sync(0xffffu, w, o);
            if (t >= o) w += y;
        }
        ws[t] = w;
    }
    __syncthreads();
    int base = wid > 0 ? ws[wid - 1] : 0;
    g_bbase[t] = base + x - v;
}
__global__ void k_scan3() {
    int i = blockIdx.x * 256 + threadIdx.x;
    int v = g_off[i] + g_bbase[i >> 8];
    g_off[i] = v;
    g_cur[i] = v;
    if (i == 0) g_off[NN] = EE;
}
__global__ void k_fill(const int* __restrict__ ei, const float* __restrict__ ew) {
    int e = blockIdx.x * blockDim.x + threadIdx.x;
    if (e < EE) {
        int r = ei[e], c = ei[EE + e];
        float2 w = ((const float2*)ew)[e];
        int pos = atomicAdd(&g_cur[c], 1);
        g_meta[pos] = make_float4(__int_as_float(r), w.x, w.y, __int_as_float(c));
    }
}
__global__ void k_degdinv() {
    int i = blockIdx.x * blockDim.x + threadIdx.x;
    if (i < NN) {
        int beg = g_off[i], end = g_off[i + 1];
        float d = 2.0f;
        for (int p = beg; p < end; p++) d += g_meta[p].z;
        g_dinv[i] = rsqrtf(d);
    }
}
__global__ void k_wprep(const float* __restrict__ cw) {
    int i = blockIdx.x * blockDim.x + threadIdx.x;
    if (i < 18432) {
        int co = i & 63;
        int ci = (i >> 6) & 31;
        int k  = i >> 11;
        int ky = k / 3, kx = k - ky * 3;
        g_wT[i] = cw[((co * 32 + ci) * 3 + ky) * 3 + kx];
    }
}

// ---------------- conv 3x3 SAME + bn2 + elu ----------------------------------
__global__ void __launch_bounds__(256)
k_conv(const float* __restrict__ x,
       const float* __restrict__ bg, const float* __restrict__ bb,
       const float* __restrict__ bm, const float* __restrict__ bv) {
    __shared__ __align__(16) float ins[32 * 204];
    __shared__ __align__(16) float wsk[2][2048];

    int tid = threadIdx.x;
    int bid = blockIdx.x;
    int xt = bid & 3;
    int y  = (bid >> 2) & 255;
    int b  = bid >> 10;
    int x0 = xt * 64;

    for (int i = tid; i < 3 * 66 * 32; i += 256) {
        int ci = i & 31;
        int p  = i >> 5;
        int r  = p / 66;
        int px = p - r * 66;
        int yy = y + r - 1;
        int xx = x0 + px - 1;
        float val = 0.f;
        if (yy >= 0 && yy < HH && xx >= 0 && xx < WW)
            val = x[(((size_t)b * HH + yy) * WW + xx) * 32 + ci];
        ins[ci * 204 + r * 68 + px] = val;
    }
    {
        const float4* wsrc = (const float4*)g_wT;
        float4* wdst = (float4*)wsk[0];
#pragma unroll
        for (int i = 0; i < 2; i++) wdst[tid + i * 256] = wsrc[tid + i * 256];
    }
    __syncthreads();

    int tx = tid & 15, ty = tid >> 4;
    int co0 = tx * 4, px0 = ty * 4;

    ull acc[4][2];
#pragma unroll
    for (int i = 0; i < 4; i++) { acc[i][0] = 0ull; acc[i][1] = 0ull; }

#pragma unroll
    for (int k = 0; k < 9; k++) {
        int buf = k & 1;
        int ky = k / 3, kx = k - ky * 3;
        const float* ipk = ins + ky * 68 + px0 + kx;
        const float* wb  = wsk[buf] + co0;
#pragma unroll 4
        for (int ci = 0; ci < 32; ci++) {
            const float* ip = ipk + ci * 204;
            float a0 = ip[0], a1 = ip[1], a2 = ip[2], a3 = ip[3];
            ulonglong2 w = *(const ulonglong2*)(wb + ci * 64);
            ull d0 = dup2(a0), d1 = dup2(a1), d2 = dup2(a2), d3 = dup2(a3);
            fma2(acc[0][0], d0, w.x); fma2(acc[0][1], d0, w.y);
            fma2(acc[1][0], d1, w.x); fma2(acc[1][1], d1, w.y);
            fma2(acc[2][0], d2, w.x); fma2(acc[2][1], d2, w.y);
            fma2(acc[3][0], d3, w.x); fma2(acc[3][1], d3, w.y);
        }
        if (k < 8) {
            const float4* wsrc = (const float4*)(g_wT + (k + 1) * 2048);
            float4* wdst = (float4*)wsk[buf ^ 1];
#pragma unroll
            for (int i = 0; i < 2; i++) wdst[tid + i * 256] = wsrc[tid + i * 256];
        }
        __syncthreads();
    }

    float sc[4], mm[4], bbv[4];
#pragma unroll
    for (int j = 0; j < 4; j++) {
        int c = co0 + j;
        sc[j]  = __ldg(&bg[c]) * rsqrtf(__ldg(&bv[c]) + 1e-5f);
        mm[j]  = __ldg(&bm[c]);
        bbv[j] = __ldg(&bb[c]);
    }
    size_t pixbase = ((size_t)b * HH + y) * WW + x0 + px0;
#pragma unroll
    for (int i = 0; i < 4; i++) {
        float2 p0 = unpack2(acc[i][0]);
        float2 p1 = unpack2(acc[i][1]);
        float r0 = eluf((p0.x - mm[0]) * sc[0] + bbv[0]);
        float r1 = eluf((p0.y - mm[1]) * sc[1] + bbv[1]);
        float r2 = eluf((p1.x - mm[2]) * sc[2] + bbv[2]);
        float r3 = eluf((p1.y - mm[3]) * sc[3] + bbv[3]);
        *(float4*)(g_h0 + (pixbase + i) * 64 + co0) = make_float4(r0, r1, r2, r3);
    }
}

// ---------------- gemm1: hw = h0 @ gcn_w.T (fp16 output) ----------------------
__global__ void __launch_bounds__(256)
k_gemm1(const float* __restrict__ in, const float* __restrict__ Wm) {
    extern __shared__ float sm[];
    float* sA = sm;               // [256][65]
    float* sW = sm + 256 * 65;    // [64][68]

    int tid = threadIdx.x;
    size_t base = (size_t)blockIdx.x * 256;

    const float4* src = (const float4*)(in + base * 64);
#pragma unroll
    for (int i = 0; i < 16; i++) {
        int idx = tid + i * 256;
        int node = idx >> 4, c4 = idx & 15;
        float4 v = src[idx];
        float* dst = &sA[node * 65 + c4 * 4];
        dst[0] = v.x; dst[1] = v.y; dst[2] = v.z; dst[3] = v.w;
    }
    const float4* w4 = (const float4*)Wm;
#pragma unroll
    for (int i = 0; i < 4; i++) {
        int idx = tid + i * 256;
        int co = idx >> 4, c4 = idx & 15;
        float4 v = w4[idx];
        sW[(c4 * 4 + 0) * 68 + co] = v.x;
        sW[(c4 * 4 + 1) * 68 + co] = v.y;
        sW[(c4 * 4 + 2) * 68 + co] = v.z;
        sW[(c4 * 4 + 3) * 68 + co] = v.w;
    }
    __syncthreads();

    int tx = tid & 7, ty = tid >> 3;
    int co0 = tx * 8, n0 = ty * 8;

    ull acc[8][4];
#pragma unroll
    for (int i = 0; i < 8; i++)
#pragma unroll
        for (int j = 0; j < 4; j++) acc[i][j] = 0ull;

    for (int ci = 0; ci < 64; ci++) {
        ulonglong2 w01 = *(const ulonglong2*)&sW[ci * 68 + co0];
        ulonglong2 w23 = *(const ulonglong2*)&sW[ci * 68 + co0 + 4];
        const float* ap = &sA[n0 * 65 + ci];
#pragma unroll
        for (int i = 0; i < 8; i++) {
            ull a = dup2(ap[i * 65]);
            fma2(acc[i][0], a, w01.x); fma2(acc[i][1], a, w01.y);
            fma2(acc[i][2], a, w23.x); fma2(acc[i][3], a, w23.y);
        }
    }
#pragma unroll
    for (int i = 0; i < 8; i++) {
        size_t node = base + n0 + i;
        float2 p0 = unpack2(acc[i][0]), p1 = unpack2(acc[i][1]);
        float2 p2 = unpack2(acc[i][2]), p3 = unpack2(acc[i][3]);
        __half2 h0 = __float22half2_rn(p0);
        __half2 h1 = __float22half2_rn(p1);
        __half2 h2 = __float22half2_rn(p2);
        __half2 h3 = __float22half2_rn(p3);
        uint4 o;
        o.x = *(unsigned*)&h0; o.y = *(unsigned*)&h1;
        o.z = *(unsigned*)&h2; o.w = *(unsigned*)&h3;
        *(uint4*)(g_hw + node * 64 + co0) = o;
    }
}

// ---------------- gcn gather (fp16 hw) ----------------
__global__ void __launch_bounds__(256)
k_gcn_gather() {
    int tid = threadIdx.x;
    int l = tid & 15;
    int node = blockIdx.x * 16 + (tid >> 4);
    int beg = g_off[node], end = g_off[node + 1];
    float dinvc = g_dinv[node];
    float s = 2.0f * dinvc * dinvc;
    uint2 hh = ((const uint2*)g_hw)[(size_t)node * 16 + l];
    float2 h0 = __half22float2(*(__half2*)&hh.x);
    float2 h1 = __half22float2(*(__half2*)&hh.y);
    float4 acc = make_float4(s * h0.x, s * h0.y, s * h1.x, s * h1.y);
    for (int p = beg; p < end; p++) {
        float4 m = g_meta[p];
        int r = __float_as_int(m.x);
        float coeff = g_dinv[r] * dinvc * m.z;
        uint2 vv = ((const uint2*)g_hw)[(size_t)r * 16 + l];
        float2 v0 = __half22float2(*(__half2*)&vv.x);
        float2 v1 = __half22float2(*(__half2*)&vv.y);
        acc.x += coeff * v0.x; acc.y += coeff * v0.y;
        acc.z += coeff * v1.x; acc.w += coeff * v1.y;
    }
    ((float4*)g_acc)[(size_t)node * 16 + l] = acc;
}

// ---------------- gemm4 (k/v written as fp16) ---------------------------------
__global__ void __launch_bounds__(256)
k_gemm4(const float* __restrict__ gb,
        const float* __restrict__ g1, const float* __restrict__ b1,
        const float* __restrict__ m1, const float* __restrict__ v1,
        const float* __restrict__ W0, const float* __restrict__ W1,
        const float* __restrict__ W2, const float* __restrict__ W3,
        const float* __restrict__ bb0, const float* __restrict__ bb1,
        const float* __restrict__ bb2, const float* __restrict__ bb3) {
    extern __shared__ float sm[];
    float* sA  = sm;                       // [256][65]
    float* sW2 = sm + 16640;               // [2][64*68]
    float* bs  = sm + 16640 + 8704;        // [4][64]
    float* pSc = bs + 256;
    float* pOf = pSc + 64;

    int tid = threadIdx.x;
    size_t base = (size_t)blockIdx.x * 256;
    const float* Wsrc[4] = {W0, W1, W2, W3};

    if (tid < 64) {
        float scv = __ldg(&g1[tid]) * rsqrtf(__ldg(&v1[tid]) + 1e-5f);
        pSc[tid] = scv;
        pOf[tid] = (__ldg(&gb[tid]) - __ldg(&m1[tid])) * scv + __ldg(&b1[tid]);
        bs[tid]       = __ldg(&bb0[tid]);
        bs[64 + tid]  = __ldg(&bb1[tid]);
        bs[128 + tid] = __ldg(&bb2[tid]);
        bs[192 + tid] = __ldg(&bb3[tid]);
    }
    __syncthreads();

    const float4* src = (const float4*)(g_acc + base * 64);
#pragma unroll
    for (int i = 0; i < 16; i++) {
        int idx = tid + i * 256;
        int node = idx >> 4, c4 = idx & 15;
        int c = c4 * 4;
        float4 v = src[idx];
        float* dst = &sA[node * 65 + c];
        dst[0] = eluf(v.x * pSc[c]     + pOf[c]);
        dst[1] = eluf(v.y * pSc[c + 1] + pOf[c + 1]);
        dst[2] = eluf(v.z * pSc[c + 2] + pOf[c + 2]);
        dst[3] = eluf(v.w * pSc[c + 3] + pOf[c + 3]);
    }
    {
        const float4* w4 = (const float4*)W0;
        float* wb = sW2;
#pragma unroll
        for (int i = 0; i < 4; i++) {
            int idx = tid + i * 256;
            int co = idx >> 4, c4 = idx & 15;
            float4 v = w4[idx];
            wb[(c4 * 4 + 0) * 68 + co] = v.x;
            wb[(c4 * 4 + 1) * 68 + co] = v.y;
            wb[(c4 * 4 + 2) * 68 + co] = v.z;
            wb[(c4 * 4 + 3) * 68 + co] = v.w;
        }
    }
    __syncthreads();

    int tx = tid & 7, ty = tid >> 3;
    int co0 = tx * 8, n0 = ty * 8;

#pragma unroll
    for (int m = 0; m < 4; m++) {
        if (m < 3) {
            const float4* w4 = (const float4*)Wsrc[m + 1];
            float* wb = sW2 + ((m + 1) & 1) * 4352;
#pragma unroll
            for (int i = 0; i < 4; i++) {
                int idx = tid + i * 256;
                int co = idx >> 4, c4 = idx & 15;
                float4 v = w4[idx];
                wb[(c4 * 4 + 0) * 68 + co] = v.x;
                wb[(c4 * 4 + 1) * 68 + co] = v.y;
                wb[(c4 * 4 + 2) * 68 + co] = v.z;
                wb[(c4 * 4 + 3) * 68 + co] = v.w;
            }
        }
        const float* wb = sW2 + (m & 1) * 4352;
        ulonglong2 bi0 = *(const ulonglong2*)&bs[m * 64 + co0];
        ulonglong2 bi1 = *(const ulonglong2*)&bs[m * 64 + co0 + 4];
        ull acc[8][4];
#pragma unroll
        for (int i = 0; i < 8; i++) {
            acc[i][0] = bi0.x; acc[i][1] = bi0.y;
            acc[i][2] = bi1.x; acc[i][3] = bi1.y;
        }
        for (int ci = 0; ci < 64; ci++) {
            ulonglong2 w01 = *(const ulonglong2*)&wb[ci * 68 + co0];
            ulonglong2 w23 = *(const ulonglong2*)&wb[ci * 68 + co0 + 4];
            const float* ap = &sA[n0 * 65 + ci];
#pragma unroll
            for (int i = 0; i < 8; i++) {
                ull a = dup2(ap[i * 65]);
                fma2(acc[i][0], a, w01.x); fma2(acc[i][1], a, w01.y);
                fma2(acc[i][2], a, w23.x); fma2(acc[i][3], a, w23.y);
            }
        }
        if (m == 0 || m == 3) {
            float* out = (m == 0) ? g_q : g_acc2;
#pragma unroll
            for (int i = 0; i < 8; i++) {
                size_t node = base + n0 + i;
                float2 p0 = unpack2(acc[i][0]), p1 = unpack2(acc[i][1]);
                float2 p2 = unpack2(acc[i][2]), p3 = unpack2(acc[i][3]);
                *(float4*)(out + node * 64 + co0)     = make_float4(p0.x, p0.y, p1.x, p1.y);
                *(float4*)(out + node * 64 + co0 + 4) = make_float4(p2.x, p2.y, p3.x, p3.y);
            }
        } else {
            __half* out = (m == 1) ? g_kh : g_vh;
#pragma unroll
            for (int i = 0; i < 8; i++) {
                size_t node = base + n0 + i;
                float2 p0 = unpack2(acc[i][0]);
                float2 p1 = unpack2(acc[i][1]);
                float2 p2 = unpack2(acc[i][2]);
                float2 p3 = unpack2(acc[i][3]);
                __half2 b0 = __float22half2_rn(p0);
                __half2 b1 = __float22half2_rn(p1);
                __half2 b2 = __float22half2_rn(p2);
                __half2 b3 = __float22half2_rn(p3);
                uint4 o;
                o.x = *(unsigned*)&b0; o.y = *(unsigned*)&b1;
                o.z = *(unsigned*)&b2; o.w = *(unsigned*)&b3;
                *(uint4*)(out + node * 64 + co0) = o;
            }
        }
        __syncthreads();
    }
}

// ---------------- fused attention: single pass, fp16 k/v gathers -------------
__global__ void __launch_bounds__(256)
k_attn(const float* __restrict__ we,
       const float* __restrict__ g1, const float* __restrict__ b1,
       const float* __restrict__ m1, const float* __restrict__ v1,
       const float* __restrict__ wl, const float* __restrict__ bl,
       float* __restrict__ out) {
    __shared__ float4 wesm4[32];
    int tid = threadIdx.x;
    if (tid < 32) wesm4[tid] = ((const float4*)we)[tid];
    __syncthreads();

    int l = tid & 15;
    int node = blockIdx.x * 16 + (tid >> 4);
    int beg = g_off[node], end = g_off[node + 1];
    unsigned mask = 0xFFFFu << (tid & 16);

    float4 q4 = ((const float4*)g_q)[(size_t)node * 16 + l];
    float4 wa = wesm4[l * 2];
    float4 wb = wesm4[l * 2 + 1];

    float qe0 = q4.x * wa.x + q4.y * wa.z + q4.z * wb.x + q4.w * wb.z;
    float qe1 = q4.x * wa.y + q4.y * wa.w + q4.z * wb.y + q4.w * wb.w;
    qe0 += __shfl_xor_sync(mask, qe0, 8); qe1 += __shfl_xor_sync(mask, qe1, 8);
    qe0 += __shfl_xor_sync(mask, qe0, 4); qe1 += __shfl_xor_sync(mask, qe1, 4);
    qe0 += __shfl_xor_sync(mask, qe0, 2); qe1 += __shfl_xor_sync(mask, qe1, 2);
    qe0 += __shfl_xor_sync(mask, qe0, 1); qe1 += __shfl_xor_sync(mask, qe1, 1);

    float d = 0.f;
    float4 acc = make_float4(0.f, 0.f, 0.f, 0.f);
    float ew0a = 0.f, ew1a = 0.f;
#pragma unroll 2
    for (int p = beg; p < end; p++) {
        float4 m = g_meta[p];
        int r = __float_as_int(m.x);
        uint2 kk = ((const uint2*)g_kh)[(size_t)r * 16 + l];
        float2 k0 = __half22float2(*(__half2*)&kk.x);
        float2 k1 = __half22float2(*(__half2*)&kk.y);
        float s = q4.x * k0.x + q4.y * k0.y + q4.z * k1.x + q4.w * k1.y;
        s += __shfl_xor_sync(mask, s, 8);
        s += __shfl_xor_sync(mask, s, 4);
        s += __shfl_xor_sync(mask, s, 2);
        s += __shfl_xor_sync(mask, s, 1);
        s = (s + qe0 * m.y + qe1 * m.z) * 0.125f;
        float f = expf(s);
        uint2 vv = ((const uint2*)g_vh)[(size_t)r * 16 + l];
        float2 v0 = __half22float2(*(__half2*)&vv.x);
        float2 v1 = __half22float2(*(__half2*)&vv.y);
        d += f;
        ew0a += f * m.y;
        ew1a += f * m.z;
        acc.x += f * v0.x; acc.y += f * v0.y;
        acc.z += f * v1.x; acc.w += f * v1.y;
    }
    float inv = d > 0.f ? 1.0f / d : 0.f;
    acc.x *= inv; acc.y *= inv; acc.z *= inv; acc.w *= inv;
    ew0a *= inv; ew1a *= inv;
    acc.x += wa.x * ew0a + wa.y * ew1a;
    acc.y += wa.z * ew0a + wa.w * ew1a;
    acc.z += wb.x * ew0a + wb.y * ew1a;
    acc.w += wb.z * ew0a + wb.w * ew1a;

    float4 skip = ((const float4*)g_acc2)[(size_t)node * 16 + l];
    int c0 = l * 4;
    float part = 0.f;
    float xv[4] = {acc.x + skip.x, acc.y + skip.y, acc.z + skip.z, acc.w + skip.w};
#pragma unroll
    for (int j = 0; j < 4; j++) {
        int c = c0 + j;
        float scv = __ldg(&g1[c]) * rsqrtf(__ldg(&v1[c]) + 1e-5f);
        float bnv = (xv[j] - __ldg(&m1[c])) * scv + __ldg(&b1[c]);
        part += bnv * __ldg(&wl[c]);
    }
    part += __shfl_xor_sync(mask, part, 8);
    part += __shfl_xor_sync(mask, part, 4);
    part += __shfl_xor_sync(mask, part, 2);
    part += __shfl_xor_sync(mask, part, 1);
    if (l == 0) out[node] = part + __ldg(&bl[0]);
}

// ---------------- host launcher (two-stream fork/join) ----------------------
extern "C" void kernel_launch(void* const* d_in, const int* in_sizes, int n_in,
                              void* d_out, int out_size) {
    (void)in_sizes; (void)n_in; (void)out_size;
    const float* x     = (const float*)d_in[0];
    const int*   ei    = (const int*)d_in[1];
    const float* ew    = (const float*)d_in[2];
    const float* cw    = (const float*)d_in[6];
    const float* bn2g  = (const float*)d_in[7];
    const float* bn2b  = (const float*)d_in[8];
    const float* bn2m  = (const float*)d_in[9];
    const float* bn2v  = (const float*)d_in[10];
    const float* gcnw  = (const float*)d_in[11];
    const float* gcnb  = (const float*)d_in[12];
    const float* bn1g  = (const float*)d_in[13];
    const float* bn1b  = (const float*)d_in[14];
    const float* bn1m  = (const float*)d_in[15];
    const float* bn1v  = (const float*)d_in[16];
    const float* wq    = (const float*)d_in[17];
    const float* bq    = (const float*)d_in[18];
    const float* wk    = (const float*)d_in[19];
    const float* bk    = (const float*)d_in[20];
    const float* wv    = (const float*)d_in[21];
    const float* bv    = (const float*)d_in[22];
    const float* we    = (const float*)d_in[23];
    const float* wsk   = (const float*)d_in[24];
    const float* bsk   = (const float*)d_in[25];
    const float* wl    = (const float*)d_in[26];
    const float* bl    = (const float*)d_in[27];

    float* p_h0;
    cudaGetSymbolAddress((void**)&p_h0, g_h0);

    const int gemm1_smem = (256 * 65 + 64 * 68) * 4;
    const int gemm4_smem = (16640 + 8704 + 256 + 128) * 4;

    static cudaStream_t s2 = nullptr;
    static cudaEvent_t evF = nullptr, evJ = nullptr;
    static bool attrSet = false;
    if (!attrSet) {
        cudaFuncSetAttribute(k_gemm1, cudaFuncAttributeMaxDynamicSharedMemorySize, gemm1_smem);
        cudaFuncSetAttribute(k_gemm4, cudaFuncAttributeMaxDynamicSharedMemorySize, gemm4_smem);
        cudaStreamCreateWithFlags(&s2, cudaStreamNonBlocking);
        cudaEventCreateWithFlags(&evF, cudaEventDisableTiming);
        cudaEventCreateWithFlags(&evJ, cudaEventDisableTiming);
        attrSet = true;
    }

    if (s2 && evF && evJ) {
        cudaEventRecord(evF, 0);
        cudaStreamWaitEvent(s2, evF, 0);
        k_init<<<NN / 256, 256, 0, s2>>>();
        k_cnt<<<EE / 256, 256, 0, s2>>>(ei);
        k_scan1<<<512, 256, 0, s2>>>();
        k_scan2<<<1, 512, 0, s2>>>();
        k_scan3<<<512, 256, 0, s2>>>();
        k_fill<<<EE / 256, 256, 0, s2>>>(ei, ew);
        k_degdinv<<<NN / 256, 256, 0, s2>>>();
        cudaEventRecord(evJ, s2);

        k_wprep<<<72, 256>>>(cw);
        k_conv<<<2048, 256>>>(x, bn2g, bn2b, bn2m, bn2v);
        k_gemm1<<<NN / 256, 256, gemm1_smem>>>(p_h0, gcnw);

        cudaStreamWaitEvent(0, evJ, 0);
    } else {
        k_init<<<NN / 256, 256>>>();
        k_cnt<<<EE / 256, 256>>>(ei);
        k_scan1<<<512, 256>>>();
        k_scan2<<<1, 512>>>();
        k_scan3<<<512, 256>>>();
        k_fill<<<EE / 256, 256>>>(ei, ew);
        k_degdinv<<<NN / 256, 256>>>();
        k_wprep<<<72, 256>>>(cw);
        k_conv<<<2048, 256>>>(x, bn2g, bn2b, bn2m, bn2v);
        k_gemm1<<<NN / 256, 256, gemm1_smem>>>(p_h0, gcnw);
    }

    k_gcn_gather<<<NN / 16, 256>>>();
    k_gemm4<<<NN / 256, 256, gemm4_smem>>>(gcnb, bn1g, bn1b, bn1m, bn1v,
                                           wq, wk, wv, wsk, bq, bk, bv, bsk);
    k_attn<<<NN / 16, 256>>>(we, bn1g, bn1b, bn1m, bn1v, wl, bl, (float*)d_out);
}

// round 14
// speedup vs baseline: 1.2689x; 1.0392x over previous
#include <cuda_runtime.h>
#include <cuda_fp16.h>
#include <math.h>

#define NN 131072
#define EE 1048576
#define HH 256
#define WW 256

typedef unsigned long long ull;

// ---------------- scratch (device globals; no allocations) ----------------
__device__ __align__(16) float g_h0[NN * 64];
__device__ __align__(16) __half g_hw[NN * 64];          // hw in fp16 (gather-only)
__device__ __align__(16) float g_q[NN * 64];
__device__ __align__(16) __half g_kh[NN * 64];          // k in fp16
__device__ __align__(16) __half g_vh[NN * 64];          // v in fp16
__device__ __align__(16) float g_acc[NN * 64];   // gcn output (pre-bn1)
__device__ __align__(16) float g_acc2[NN * 64];  // skip projection
__device__ __align__(16) float g_dinv[NN];
__device__ __align__(16) float g_wT[9 * 32 * 64];
// CSR (by destination col)
__device__ __align__(16) int    g_cnt[NN];
__device__ __align__(16) int    g_off[NN + 1];
__device__ __align__(16) int    g_cur[NN];
__device__ __align__(16) int    g_bsum[512];
__device__ __align__(16) int    g_bbase[512];
__device__ __align__(16) float4 g_meta[EE];      // {src bits, ew0, ew1, dst bits}

__device__ __forceinline__ float eluf(float x) {
    return x > 0.f ? x : 0.1f * expm1f(x);
}
__device__ __forceinline__ void fma2(ull& acc, ull a, ull w) {
    asm("fma.rn.f32x2 %0, %1, %2, %0;" : "+l"(acc) : "l"(a), "l"(w));
}
__device__ __forceinline__ ull dup2(float a) {
    ull r; asm("mov.b64 %0, {%1, %1};" : "=l"(r) : "f"(a)); return r;
}
__device__ __forceinline__ float2 unpack2(ull v) {
    float2 r; asm("mov.b64 {%0, %1}, %2;" : "=f"(r.x), "=f"(r.y) : "l"(v)); return r;
}

// ---------------- CSR build chain ----------------
__global__ void k_init() {
    int i = blockIdx.x * blockDim.x + threadIdx.x;
    if (i < NN) g_cnt[i] = 0;
}
__global__ void k_cnt(const int* __restrict__ ei) {
    int e = blockIdx.x * blockDim.x + threadIdx.x;
    if (e < EE) atomicAdd(&g_cnt[ei[EE + e]], 1);
}
__global__ void k_scan1() {
    int b = blockIdx.x, t = threadIdx.x;
    int i = b * 256 + t;
    int v = g_cnt[i];
    int lane = t & 31, wid = t >> 5;
    int x = v;
#pragma unroll
    for (int o = 1; o < 32; o <<= 1) {
        int y = __shfl_up_sync(0xffffffffu, x, o);
        if (lane >= o) x += y;
    }
    __shared__ int wsum[8];
    if (lane == 31) wsum[wid] = x;
    __syncthreads();
    if (t < 8) {
        int w = wsum[t];
#pragma unroll
        for (int o = 1; o < 8; o <<= 1) {
            int y = __shfl_up_sync(0xffu, w, o);
            if (t >= o) w += y;
        }
        wsum[t] = w;
    }
    __syncthreads();
    int base = wid > 0 ? wsum[wid - 1] : 0;
    int incl = base + x;
    g_off[i] = incl - v;
    if (t == 255) g_bsum[b] = incl;
}
__global__ void k_scan2() {
    int t = threadIdx.x;
    int v = g_bsum[t];
    int lane = t & 31, wid = t >> 5;
    int x = v;
#pragma unroll
    for (int o = 1; o < 32; o <<= 1) {
        int y = __shfl_up_sync(0xffffffffu, x, o);
        if (lane >= o) x += y;
    }
    __shared__ int ws[16];
    if (lane == 31) ws[wid] = x;
    __syncthreads();
    if (t < 16) {
        int w = ws[t];
#pragma unroll
        for (int o = 1; o < 16; o <<= 1) {
            int y = __shfl_up_sync(0xffffu, w, o);
            if (t >= o) w += y;
        }
        ws[t] = w;
    }
    __syncthreads();
    int base = wid > 0 ? ws[wid - 1] : 0;
    g_bbase[t] = base + x - v;
}
__global__ void k_scan3() {
    int i = blockIdx.x * 256 + threadIdx.x;
    int v = g_off[i] + g_bbase[i >> 8];
    g_off[i] = v;
    g_cur[i] = v;
    if (i == 0) g_off[NN] = EE;
}
__global__ void k_fill(const int* __restrict__ ei, const float* __restrict__ ew) {
    int e = blockIdx.x * blockDim.x + threadIdx.x;
    if (e < EE) {
        int r = ei[e], c = ei[EE + e];
        float2 w = ((const float2*)ew)[e];
        int pos = atomicAdd(&g_cur[c], 1);
        g_meta[pos] = make_float4(__int_as_float(r), w.x, w.y, __int_as_float(c));
    }
}
__global__ void k_degdinv() {
    int i = blockIdx.x * blockDim.x + threadIdx.x;
    if (i < NN) {
        int beg = g_off[i], end = g_off[i + 1];
        float d = 2.0f;
        for (int p = beg; p < end; p++) d += g_meta[p].z;
        g_dinv[i] = rsqrtf(d);
    }
}
__global__ void k_wprep(const float* __restrict__ cw) {
    int i = blockIdx.x * blockDim.x + threadIdx.x;
    if (i < 18432) {
        int co = i & 63;
        int ci = (i >> 6) & 31;
        int k  = i >> 11;
        int ky = k / 3, kx = k - ky * 3;
        g_wT[i] = cw[((co * 32 + ci) * 3 + ky) * 3 + kx];
    }
}

// ---------------- conv 3x3 SAME + bn2 + elu ------------------------------------
// Per-ky weight staging (3 kx resident, 24KB) + kx register reuse of inputs.
// smem = 26KB halo + 24KB weights = 50KB -> 4 CTA/SM.
__global__ void __launch_bounds__(256)
k_conv(const float* __restrict__ x,
       const float* __restrict__ bg, const float* __restrict__ bb,
       const float* __restrict__ bm, const float* __restrict__ bv) {
    __shared__ __align__(16) float ins[32 * 204];
    __shared__ __align__(16) float wsk[3 * 2048];   // 3 kx of current ky

    int tid = threadIdx.x;
    int bid = blockIdx.x;
    int xt = bid & 3;
    int y  = (bid >> 2) & 255;
    int b  = bid >> 10;
    int x0 = xt * 64;

    for (int i = tid; i < 3 * 66 * 32; i += 256) {
        int ci = i & 31;
        int p  = i >> 5;
        int r  = p / 66;
        int px = p - r * 66;
        int yy = y + r - 1;
        int xx = x0 + px - 1;
        float val = 0.f;
        if (yy >= 0 && yy < HH && xx >= 0 && xx < WW)
            val = x[(((size_t)b * HH + yy) * WW + xx) * 32 + ci];
        ins[ci * 204 + r * 68 + px] = val;
    }

    int tx = tid & 15, ty = tid >> 4;
    int co0 = tx * 4, px0 = ty * 4;

    ull acc[4][2];
#pragma unroll
    for (int i = 0; i < 4; i++) { acc[i][0] = 0ull; acc[i][1] = 0ull; }

#pragma unroll
    for (int ky = 0; ky < 3; ky++) {
        // stage weights for this ky (3 kx = 6144 floats = 1536 float4)
        if (ky > 0) __syncthreads();      // protect previous wsk use
        {
            const float4* wsrc = (const float4*)(g_wT + ky * 3 * 2048);
            float4* wdst = (float4*)wsk;
#pragma unroll
            for (int i = 0; i < 6; i++) wdst[tid + i * 256] = wsrc[tid + i * 256];
        }
        __syncthreads();

        const float* ipk = ins + ky * 68 + px0;
#pragma unroll 2
        for (int ci = 0; ci < 32; ci++) {
            const float* ip = ipk + ci * 204;
            float a0 = ip[0], a1 = ip[1], a2 = ip[2];
            float a3 = ip[3], a4 = ip[4], a5 = ip[5];
            ull d[6];
            d[0] = dup2(a0); d[1] = dup2(a1); d[2] = dup2(a2);
            d[3] = dup2(a3); d[4] = dup2(a4); d[5] = dup2(a5);
#pragma unroll
            for (int kx = 0; kx < 3; kx++) {
                ulonglong2 w = *(const ulonglong2*)&wsk[kx * 2048 + ci * 64 + co0];
                fma2(acc[0][0], d[kx + 0], w.x); fma2(acc[0][1], d[kx + 0], w.y);
                fma2(acc[1][0], d[kx + 1], w.x); fma2(acc[1][1], d[kx + 1], w.y);
                fma2(acc[2][0], d[kx + 2], w.x); fma2(acc[2][1], d[kx + 2], w.y);
                fma2(acc[3][0], d[kx + 3], w.x); fma2(acc[3][1], d[kx + 3], w.y);
            }
        }
    }

    float sc[4], mm[4], bbv[4];
#pragma unroll
    for (int j = 0; j < 4; j++) {
        int c = co0 + j;
        sc[j]  = __ldg(&bg[c]) * rsqrtf(__ldg(&bv[c]) + 1e-5f);
        mm[j]  = __ldg(&bm[c]);
        bbv[j] = __ldg(&bb[c]);
    }
    size_t pixbase = ((size_t)b * HH + y) * WW + x0 + px0;
#pragma unroll
    for (int i = 0; i < 4; i++) {
        float2 p0 = unpack2(acc[i][0]);
        float2 p1 = unpack2(acc[i][1]);
        float r0 = eluf((p0.x - mm[0]) * sc[0] + bbv[0]);
        float r1 = eluf((p0.y - mm[1]) * sc[1] + bbv[1]);
        float r2 = eluf((p1.x - mm[2]) * sc[2] + bbv[2]);
        float r3 = eluf((p1.y - mm[3]) * sc[3] + bbv[3]);
        *(float4*)(g_h0 + (pixbase + i) * 64 + co0) = make_float4(r0, r1, r2, r3);
    }
}

// ---------------- gemm1: hw = h0 @ gcn_w.T (fp16 output) ----------------------
__global__ void __launch_bounds__(256)
k_gemm1(const float* __restrict__ in, const float* __restrict__ Wm) {
    extern __shared__ float sm[];
    float* sA = sm;               // [256][65]
    float* sW = sm + 256 * 65;    // [64][68]

    int tid = threadIdx.x;
    size_t base = (size_t)blockIdx.x * 256;

    const float4* src = (const float4*)(in + base * 64);
#pragma unroll
    for (int i = 0; i < 16; i++) {
        int idx = tid + i * 256;
        int node = idx >> 4, c4 = idx & 15;
        float4 v = src[idx];
        float* dst = &sA[node * 65 + c4 * 4];
        dst[0] = v.x; dst[1] = v.y; dst[2] = v.z; dst[3] = v.w;
    }
    const float4* w4 = (const float4*)Wm;
#pragma unroll
    for (int i = 0; i < 4; i++) {
        int idx = tid + i * 256;
        int co = idx >> 4, c4 = idx & 15;
        float4 v = w4[idx];
        sW[(c4 * 4 + 0) * 68 + co] = v.x;
        sW[(c4 * 4 + 1) * 68 + co] = v.y;
        sW[(c4 * 4 + 2) * 68 + co] = v.z;
        sW[(c4 * 4 + 3) * 68 + co] = v.w;
    }
    __syncthreads();

    int tx = tid & 7, ty = tid >> 3;
    int co0 = tx * 8, n0 = ty * 8;

    ull acc[8][4];
#pragma unroll
    for (int i = 0; i < 8; i++)
#pragma unroll
        for (int j = 0; j < 4; j++) acc[i][j] = 0ull;

    for (int ci = 0; ci < 64; ci++) {
        ulonglong2 w01 = *(const ulonglong2*)&sW[ci * 68 + co0];
        ulonglong2 w23 = *(const ulonglong2*)&sW[ci * 68 + co0 + 4];
        const float* ap = &sA[n0 * 65 + ci];
#pragma unroll
        for (int i = 0; i < 8; i++) {
            ull a = dup2(ap[i * 65]);
            fma2(acc[i][0], a, w01.x); fma2(acc[i][1], a, w01.y);
            fma2(acc[i][2], a, w23.x); fma2(acc[i][3], a, w23.y);
        }
    }
#pragma unroll
    for (int i = 0; i < 8; i++) {
        size_t node = base + n0 + i;
        float2 p0 = unpack2(acc[i][0]), p1 = unpack2(acc[i][1]);
        float2 p2 = unpack2(acc[i][2]), p3 = unpack2(acc[i][3]);
        __half2 h0 = __float22half2_rn(p0);
        __half2 h1 = __float22half2_rn(p1);
        __half2 h2 = __float22half2_rn(p2);
        __half2 h3 = __float22half2_rn(p3);
        uint4 o;
        o.x = *(unsigned*)&h0; o.y = *(unsigned*)&h1;
        o.z = *(unsigned*)&h2; o.w = *(unsigned*)&h3;
        *(uint4*)(g_hw + node * 64 + co0) = o;
    }
}

// ---------------- gcn gather (fp16 hw) ----------------
__global__ void __launch_bounds__(256)
k_gcn_gather() {
    int tid = threadIdx.x;
    int l = tid & 15;
    int node = blockIdx.x * 16 + (tid >> 4);
    int beg = g_off[node], end = g_off[node + 1];
    float dinvc = g_dinv[node];
    float s = 2.0f * dinvc * dinvc;
    uint2 hh = ((const uint2*)g_hw)[(size_t)node * 16 + l];
    float2 h0 = __half22float2(*(__half2*)&hh.x);
    float2 h1 = __half22float2(*(__half2*)&hh.y);
    float4 acc = make_float4(s * h0.x, s * h0.y, s * h1.x, s * h1.y);
    for (int p = beg; p < end; p++) {
        float4 m = g_meta[p];
        int r = __float_as_int(m.x);
        float coeff = g_dinv[r] * dinvc * m.z;
        uint2 vv = ((const uint2*)g_hw)[(size_t)r * 16 + l];
        float2 v0 = __half22float2(*(__half2*)&vv.x);
        float2 v1 = __half22float2(*(__half2*)&vv.y);
        acc.x += coeff * v0.x; acc.y += coeff * v0.y;
        acc.z += coeff * v1.x; acc.w += coeff * v1.y;
    }
    ((float4*)g_acc)[(size_t)node * 16 + l] = acc;
}

// ---------------- gemm4 (k/v written as fp16) ---------------------------------
__global__ void __launch_bounds__(256)
k_gemm4(const float* __restrict__ gb,
        const float* __restrict__ g1, const float* __restrict__ b1,
        const float* __restrict__ m1, const float* __restrict__ v1,
        const float* __restrict__ W0, const float* __restrict__ W1,
        const float* __restrict__ W2, const float* __restrict__ W3,
        const float* __restrict__ bb0, const float* __restrict__ bb1,
        const float* __restrict__ bb2, const float* __restrict__ bb3) {
    extern __shared__ float sm[];
    float* sA  = sm;                       // [256][65]
    float* sW2 = sm + 16640;               // [2][64*68]
    float* bs  = sm + 16640 + 8704;        // [4][64]
    float* pSc = bs + 256;
    float* pOf = pSc + 64;

    int tid = threadIdx.x;
    size_t base = (size_t)blockIdx.x * 256;
    const float* Wsrc[4] = {W0, W1, W2, W3};

    if (tid < 64) {
        float scv = __ldg(&g1[tid]) * rsqrtf(__ldg(&v1[tid]) + 1e-5f);
        pSc[tid] = scv;
        pOf[tid] = (__ldg(&gb[tid]) - __ldg(&m1[tid])) * scv + __ldg(&b1[tid]);
        bs[tid]       = __ldg(&bb0[tid]);
        bs[64 + tid]  = __ldg(&bb1[tid]);
        bs[128 + tid] = __ldg(&bb2[tid]);
        bs[192 + tid] = __ldg(&bb3[tid]);
    }
    __syncthreads();

    const float4* src = (const float4*)(g_acc + base * 64);
#pragma unroll
    for (int i = 0; i < 16; i++) {
        int idx = tid + i * 256;
        int node = idx >> 4, c4 = idx & 15;
        int c = c4 * 4;
        float4 v = src[idx];
        float* dst = &sA[node * 65 + c];
        dst[0] = eluf(v.x * pSc[c]     + pOf[c]);
        dst[1] = eluf(v.y * pSc[c + 1] + pOf[c + 1]);
        dst[2] = eluf(v.z * pSc[c + 2] + pOf[c + 2]);
        dst[3] = eluf(v.w * pSc[c + 3] + pOf[c + 3]);
    }
    {
        const float4* w4 = (const float4*)W0;
        float* wb = sW2;
#pragma unroll
        for (int i = 0; i < 4; i++) {
            int idx = tid + i * 256;
            int co = idx >> 4, c4 = idx & 15;
            float4 v = w4[idx];
            wb[(c4 * 4 + 0) * 68 + co] = v.x;
            wb[(c4 * 4 + 1) * 68 + co] = v.y;
            wb[(c4 * 4 + 2) * 68 + co] = v.z;
            wb[(c4 * 4 + 3) * 68 + co] = v.w;
        }
    }
    __syncthreads();

    int tx = tid & 7, ty = tid >> 3;
    int co0 = tx * 8, n0 = ty * 8;

#pragma unroll
    for (int m = 0; m < 4; m++) {
        if (m < 3) {
            const float4* w4 = (const float4*)Wsrc[m + 1];
            float* wb = sW2 + ((m + 1) & 1) * 4352;
#pragma unroll
            for (int i = 0; i < 4; i++) {
                int idx = tid + i * 256;
                int co = idx >> 4, c4 = idx & 15;
                float4 v = w4[idx];
                wb[(c4 * 4 + 0) * 68 + co] = v.x;
                wb[(c4 * 4 + 1) * 68 + co] = v.y;
                wb[(c4 * 4 + 2) * 68 + co] = v.z;
                wb[(c4 * 4 + 3) * 68 + co] = v.w;
            }
        }
        const float* wb = sW2 + (m & 1) * 4352;
        ulonglong2 bi0 = *(const ulonglong2*)&bs[m * 64 + co0];
        ulonglong2 bi1 = *(const ulonglong2*)&bs[m * 64 + co0 + 4];
        ull acc[8][4];
#pragma unroll
        for (int i = 0; i < 8; i++) {
            acc[i][0] = bi0.x; acc[i][1] = bi0.y;
            acc[i][2] = bi1.x; acc[i][3] = bi1.y;
        }
        for (int ci = 0; ci < 64; ci++) {
            ulonglong2 w01 = *(const ulonglong2*)&wb[ci * 68 + co0];
            ulonglong2 w23 = *(const ulonglong2*)&wb[ci * 68 + co0 + 4];
            const float* ap = &sA[n0 * 65 + ci];
#pragma unroll
            for (int i = 0; i < 8; i++) {
                ull a = dup2(ap[i * 65]);
                fma2(acc[i][0], a, w01.x); fma2(acc[i][1], a, w01.y);
                fma2(acc[i][2], a, w23.x); fma2(acc[i][3], a, w23.y);
            }
        }
        if (m == 0 || m == 3) {
            float* out = (m == 0) ? g_q : g_acc2;
#pragma unroll
            for (int i = 0; i < 8; i++) {
                size_t node = base + n0 + i;
                float2 p0 = unpack2(acc[i][0]), p1 = unpack2(acc[i][1]);
                float2 p2 = unpack2(acc[i][2]), p3 = unpack2(acc[i][3]);
                *(float4*)(out + node * 64 + co0)     = make_float4(p0.x, p0.y, p1.x, p1.y);
                *(float4*)(out + node * 64 + co0 + 4) = make_float4(p2.x, p2.y, p3.x, p3.y);
            }
        } else {
            __half* out = (m == 1) ? g_kh : g_vh;
#pragma unroll
            for (int i = 0; i < 8; i++) {
                size_t node = base + n0 + i;
                float2 p0 = unpack2(acc[i][0]);
                float2 p1 = unpack2(acc[i][1]);
                float2 p2 = unpack2(acc[i][2]);
                float2 p3 = unpack2(acc[i][3]);
                __half2 b0 = __float22half2_rn(p0);
                __half2 b1 = __float22half2_rn(p1);
                __half2 b2 = __float22half2_rn(p2);
                __half2 b3 = __float22half2_rn(p3);
                uint4 o;
                o.x = *(unsigned*)&b0; o.y = *(unsigned*)&b1;
                o.z = *(unsigned*)&b2; o.w = *(unsigned*)&b3;
                *(uint4*)(out + node * 64 + co0) = o;
            }
        }
        __syncthreads();
    }
}

// ---------------- fused attention: single pass, fp16 k/v gathers -------------
__global__ void __launch_bounds__(256)
k_attn(const float* __restrict__ we,
       const float* __restrict__ g1, const float* __restrict__ b1,
       const float* __restrict__ m1, const float* __restrict__ v1,
       const float* __restrict__ wl, const float* __restrict__ bl,
       float* __restrict__ out) {
    __shared__ float4 wesm4[32];
    int tid = threadIdx.x;
    if (tid < 32) wesm4[tid] = ((const float4*)we)[tid];
    __syncthreads();

    int l = tid & 15;
    int node = blockIdx.x * 16 + (tid >> 4);
    int beg = g_off[node], end = g_off[node + 1];
    unsigned mask = 0xFFFFu << (tid & 16);

    float4 q4 = ((const float4*)g_q)[(size_t)node * 16 + l];
    float4 wa = wesm4[l * 2];
    float4 wb = wesm4[l * 2 + 1];

    float qe0 = q4.x * wa.x + q4.y * wa.z + q4.z * wb.x + q4.w * wb.z;
    float qe1 = q4.x * wa.y + q4.y * wa.w + q4.z * wb.y + q4.w * wb.w;
    qe0 += __shfl_xor_sync(mask, qe0, 8); qe1 += __shfl_xor_sync(mask, qe1, 8);
    qe0 += __shfl_xor_sync(mask, qe0, 4); qe1 += __shfl_xor_sync(mask, qe1, 4);
    qe0 += __shfl_xor_sync(mask, qe0, 2); qe1 += __shfl_xor_sync(mask, qe1, 2);
    qe0 += __shfl_xor_sync(mask, qe0, 1); qe1 += __shfl_xor_sync(mask, qe1, 1);

    float d = 0.f;
    float4 acc = make_float4(0.f, 0.f, 0.f, 0.f);
    float ew0a = 0.f, ew1a = 0.f;
#pragma unroll 2
    for (int p = beg; p < end; p++) {
        float4 m = g_meta[p];
        int r = __float_as_int(m.x);
        uint2 kk = ((const uint2*)g_kh)[(size_t)r * 16 + l];
        float2 k0 = __half22float2(*(__half2*)&kk.x);
        float2 k1 = __half22float2(*(__half2*)&kk.y);
        float s = q4.x * k0.x + q4.y * k0.y + q4.z * k1.x + q4.w * k1.y;
        s += __shfl_xor_sync(mask, s, 8);
        s += __shfl_xor_sync(mask, s, 4);
        s += __shfl_xor_sync(mask, s, 2);
        s += __shfl_xor_sync(mask, s, 1);
        s = (s + qe0 * m.y + qe1 * m.z) * 0.125f;
        float f = expf(s);
        uint2 vv = ((const uint2*)g_vh)[(size_t)r * 16 + l];
        float2 v0 = __half22float2(*(__half2*)&vv.x);
        float2 v1 = __half22float2(*(__half2*)&vv.y);
        d += f;
        ew0a += f * m.y;
        ew1a += f * m.z;
        acc.x += f * v0.x; acc.y += f * v0.y;
        acc.z += f * v1.x; acc.w += f * v1.y;
    }
    float inv = d > 0.f ? 1.0f / d : 0.f;
    acc.x *= inv; acc.y *= inv; acc.z *= inv; acc.w *= inv;
    ew0a *= inv; ew1a *= inv;
    acc.x += wa.x * ew0a + wa.y * ew1a;
    acc.y += wa.z * ew0a + wa.w * ew1a;
    acc.z += wb.x * ew0a + wb.y * ew1a;
    acc.w += wb.z * ew0a + wb.w * ew1a;

    float4 skip = ((const float4*)g_acc2)[(size_t)node * 16 + l];
    int c0 = l * 4;
    float part = 0.f;
    float xv[4] = {acc.x + skip.x, acc.y + skip.y, acc.z + skip.z, acc.w + skip.w};
#pragma unroll
    for (int j = 0; j < 4; j++) {
        int c = c0 + j;
        float scv = __ldg(&g1[c]) * rsqrtf(__ldg(&v1[c]) + 1e-5f);
        float bnv = (xv[j] - __ldg(&m1[c])) * scv + __ldg(&b1[c]);
        part += bnv * __ldg(&wl[c]);
    }
    part += __shfl_xor_sync(mask, part, 8);
    part += __shfl_xor_sync(mask, part, 4);
    part += __shfl_xor_sync(mask, part, 2);
    part += __shfl_xor_sync(mask, part, 1);
    if (l == 0) out[node] = part + __ldg(&bl[0]);
}

// ---------------- host launcher (two-stream fork/join) ----------------------
extern "C" void kernel_launch(void* const* d_in, const int* in_sizes, int n_in,
                              void* d_out, int out_size) {
    (void)in_sizes; (void)n_in; (void)out_size;
    const float* x     = (const float*)d_in[0];
    const int*   ei    = (const int*)d_in[1];
    const float* ew    = (const float*)d_in[2];
    const float* cw    = (const float*)d_in[6];
    const float* bn2g  = (const float*)d_in[7];
    const float* bn2b  = (const float*)d_in[8];
    const float* bn2m  = (const float*)d_in[9];
    const float* bn2v  = (const float*)d_in[10];
    const float* gcnw  = (const float*)d_in[11];
    const float* gcnb  = (const float*)d_in[12];
    const float* bn1g  = (const float*)d_in[13];
    const float* bn1b  = (const float*)d_in[14];
    const float* bn1m  = (const float*)d_in[15];
    const float* bn1v  = (const float*)d_in[16];
    const float* wq    = (const float*)d_in[17];
    const float* bq    = (const float*)d_in[18];
    const float* wk    = (const float*)d_in[19];
    const float* bk    = (const float*)d_in[20];
    const float* wv    = (const float*)d_in[21];
    const float* bv    = (const float*)d_in[22];
    const float* we    = (const float*)d_in[23];
    const float* wsk   = (const float*)d_in[24];
    const float* bsk   = (const float*)d_in[25];
    const float* wl    = (const float*)d_in[26];
    const float* bl    = (const float*)d_in[27];

    float* p_h0;
    cudaGetSymbolAddress((void**)&p_h0, g_h0);

    const int gemm1_smem = (256 * 65 + 64 * 68) * 4;
    const int gemm4_smem = (16640 + 8704 + 256 + 128) * 4;

    static cudaStream_t s2 = nullptr;
    static cudaEvent_t evF = nullptr, evJ = nullptr;
    static bool attrSet = false;
    if (!attrSet) {
        cudaFuncSetAttribute(k_gemm1, cudaFuncAttributeMaxDynamicSharedMemorySize, gemm1_smem);
        cudaFuncSetAttribute(k_gemm4, cudaFuncAttributeMaxDynamicSharedMemorySize, gemm4_smem);
        cudaStreamCreateWithFlags(&s2, cudaStreamNonBlocking);
        cudaEventCreateWithFlags(&evF, cudaEventDisableTiming);
        cudaEventCreateWithFlags(&evJ, cudaEventDisableTiming);
        attrSet = true;
    }

    if (s2 && evF && evJ) {
        cudaEventRecord(evF, 0);
        cudaStreamWaitEvent(s2, evF, 0);
        k_init<<<NN / 256, 256, 0, s2>>>();
        k_cnt<<<EE / 256, 256, 0, s2>>>(ei);
        k_scan1<<<512, 256, 0, s2>>>();
        k_scan2<<<1, 512, 0, s2>>>();
        k_scan3<<<512, 256, 0, s2>>>();
        k_fill<<<EE / 256, 256, 0, s2>>>(ei, ew);
        k_degdinv<<<NN / 256, 256, 0, s2>>>();
        cudaEventRecord(evJ, s2);

        k_wprep<<<72, 256>>>(cw);
        k_conv<<<2048, 256>>>(x, bn2g, bn2b, bn2m, bn2v);
        k_gemm1<<<NN / 256, 256, gemm1_smem>>>(p_h0, gcnw);

        cudaStreamWaitEvent(0, evJ, 0);
    } else {
        k_init<<<NN / 256, 256>>>();
        k_cnt<<<EE / 256, 256>>>(ei);
        k_scan1<<<512, 256>>>();
        k_scan2<<<1, 512>>>();
        k_scan3<<<512, 256>>>();
        k_fill<<<EE / 256, 256>>>(ei, ew);
        k_degdinv<<<NN / 256, 256>>>();
        k_wprep<<<72, 256>>>(cw);
        k_conv<<<2048, 256>>>(x, bn2g, bn2b, bn2m, bn2v);
        k_gemm1<<<NN / 256, 256, gemm1_smem>>>(p_h0, gcnw);
    }

    k_gcn_gather<<<NN / 16, 256>>>();
    k_gemm4<<<NN / 256, 256, gemm4_smem>>>(gcnb, bn1g, bn1b, bn1m, bn1v,
                                           wq, wk, wv, wsk, bq, bk, bv, bsk);
    k_attn<<<NN / 16, 256>>>(we, bn1g, bn1b, bn1m, bn1v, wl, bl, (float*)d_out);
}

// round 15
// speedup vs baseline: 1.3067x; 1.0298x over previous
#include <cuda_runtime.h>
#include <cuda_fp16.h>
#include <math.h>

#define NN 131072
#define EE 1048576
#define HH 256
#define WW 256

typedef unsigned long long ull;

// ---------------- scratch (device globals; no allocations) ----------------
__device__ __align__(16) __half g_h0[NN * 64];          // conv out (fp16 stream)
__device__ __align__(16) __half g_hw[NN * 64];          // hw in fp16 (gathered)
__device__ __align__(16) float g_q[NN * 64];            // q fp32 (precision-critical)
__device__ __align__(16) __half g_kh[NN * 64];          // k fp16 (gathered)
__device__ __align__(16) __half g_vh[NN * 64];          // v fp16 (gathered)
__device__ __align__(16) __half g_acc[NN * 64];         // gcn out (fp16 stream)
__device__ __align__(16) __half g_acc2[NN * 64];        // skip (fp16 stream)
__device__ __align__(16) float g_dinv[NN];
__device__ __align__(16) float g_wT[9 * 32 * 64];
// CSR (by destination col)
__device__ __align__(16) int    g_cnt[NN];
__device__ __align__(16) int    g_off[NN + 1];
__device__ __align__(16) int    g_cur[NN];
__device__ __align__(16) int    g_bsum[512];
__device__ __align__(16) int    g_bbase[512];
__device__ __align__(16) float4 g_meta[EE];      // {src bits, ew0, ew1, dst bits}

__device__ __forceinline__ float eluf(float x) {
    return x > 0.f ? x : 0.1f * expm1f(x);
}
__device__ __forceinline__ void fma2(ull& acc, ull a, ull w) {
    asm("fma.rn.f32x2 %0, %1, %2, %0;" : "+l"(acc) : "l"(a), "l"(w));
}
__device__ __forceinline__ ull dup2(float a) {
    ull r; asm("mov.b64 %0, {%1, %1};" : "=l"(r) : "f"(a)); return r;
}
__device__ __forceinline__ float2 unpack2(ull v) {
    float2 r; asm("mov.b64 {%0, %1}, %2;" : "=f"(r.x), "=f"(r.y) : "l"(v)); return r;
}
__device__ __forceinline__ unsigned h2pack(float a, float b) {
    __half2 h = __floats2half2_rn(a, b);
    return *(unsigned*)&h;
}

// ---------------- CSR build chain ----------------
__global__ void k_init() {
    int i = blockIdx.x * blockDim.x + threadIdx.x;
    if (i < NN) g_cnt[i] = 0;
}
__global__ void k_cnt(const int* __restrict__ ei) {
    int e = blockIdx.x * blockDim.x + threadIdx.x;
    if (e < EE) atomicAdd(&g_cnt[ei[EE + e]], 1);
}
__global__ void k_scan1() {
    int b = blockIdx.x, t = threadIdx.x;
    int i = b * 256 + t;
    int v = g_cnt[i];
    int lane = t & 31, wid = t >> 5;
    int x = v;
#pragma unroll
    for (int o = 1; o < 32; o <<= 1) {
        int y = __shfl_up_sync(0xffffffffu, x, o);
        if (lane >= o) x += y;
    }
    __shared__ int wsum[8];
    if (lane == 31) wsum[wid] = x;
    __syncthreads();
    if (t < 8) {
        int w = wsum[t];
#pragma unroll
        for (int o = 1; o < 8; o <<= 1) {
            int y = __shfl_up_sync(0xffu, w, o);
            if (t >= o) w += y;
        }
        wsum[t] = w;
    }
    __syncthreads();
    int base = wid > 0 ? wsum[wid - 1] : 0;
    int incl = base + x;
    g_off[i] = incl - v;
    if (t == 255) g_bsum[b] = incl;
}
__global__ void k_scan2() {
    int t = threadIdx.x;
    int v = g_bsum[t];
    int lane = t & 31, wid = t >> 5;
    int x = v;
#pragma unroll
    for (int o = 1; o < 32; o <<= 1) {
        int y = __shfl_up_sync(0xffffffffu, x, o);
        if (lane >= o) x += y;
    }
    __shared__ int ws[16];
    if (lane == 31) ws[wid] = x;
    __syncthreads();
    if (t < 16) {
        int w = ws[t];
#pragma unroll
        for (int o = 1; o < 16; o <<= 1) {
            int y = __shfl_up_sync(0xffffu, w, o);
            if (t >= o) w += y;
        }
        ws[t] = w;
    }
    __syncthreads();
    int base = wid > 0 ? ws[wid - 1] : 0;
    g_bbase[t] = base + x - v;
}
__global__ void k_scan3() {
    int i = blockIdx.x * 256 + threadIdx.x;
    int v = g_off[i] + g_bbase[i >> 8];
    g_off[i] = v;
    g_cur[i] = v;
    if (i == 0) g_off[NN] = EE;
}
__global__ void k_fill(const int* __restrict__ ei, const float* __restrict__ ew) {
    int e = blockIdx.x * blockDim.x + threadIdx.x;
    if (e < EE) {
        int r = ei[e], c = ei[EE + e];
        float2 w = ((const float2*)ew)[e];
        int pos = atomicAdd(&g_cur[c], 1);
        g_meta[pos] = make_float4(__int_as_float(r), w.x, w.y, __int_as_float(c));
    }
}
__global__ void k_degdinv() {
    int i = blockIdx.x * blockDim.x + threadIdx.x;
    if (i < NN) {
        int beg = g_off[i], end = g_off[i + 1];
        float d = 2.0f;
        for (int p = beg; p < end; p++) d += g_meta[p].z;
        g_dinv[i] = rsqrtf(d);
    }
}
__global__ void k_wprep(const float* __restrict__ cw) {
    int i = blockIdx.x * blockDim.x + threadIdx.x;
    if (i < 18432) {
        int co = i & 63;
        int ci = (i >> 6) & 31;
        int k  = i >> 11;
        int ky = k / 3, kx = k - ky * 3;
        g_wT[i] = cw[((co * 32 + ci) * 3 + ky) * 3 + kx];
    }
}

// ---------------- conv 3x3 SAME + bn2 + elu (per-ky staging, fp16 out) -------
__global__ void __launch_bounds__(256)
k_conv(const float* __restrict__ x,
       const float* __restrict__ bg, const float* __restrict__ bb,
       const float* __restrict__ bm, const float* __restrict__ bv) {
    __shared__ __align__(16) float ins[32 * 204];
    __shared__ __align__(16) float wsk[3 * 2048];

    int tid = threadIdx.x;
    int bid = blockIdx.x;
    int xt = bid & 3;
    int y  = (bid >> 2) & 255;
    int b  = bid >> 10;
    int x0 = xt * 64;

    for (int i = tid; i < 3 * 66 * 32; i += 256) {
        int ci = i & 31;
        int p  = i >> 5;
        int r  = p / 66;
        int px = p - r * 66;
        int yy = y + r - 1;
        int xx = x0 + px - 1;
        float val = 0.f;
        if (yy >= 0 && yy < HH && xx >= 0 && xx < WW)
            val = x[(((size_t)b * HH + yy) * WW + xx) * 32 + ci];
        ins[ci * 204 + r * 68 + px] = val;
    }

    int tx = tid & 15, ty = tid >> 4;
    int co0 = tx * 4, px0 = ty * 4;

    ull acc[4][2];
#pragma unroll
    for (int i = 0; i < 4; i++) { acc[i][0] = 0ull; acc[i][1] = 0ull; }

#pragma unroll
    for (int ky = 0; ky < 3; ky++) {
        if (ky > 0) __syncthreads();
        {
            const float4* wsrc = (const float4*)(g_wT + ky * 3 * 2048);
            float4* wdst = (float4*)wsk;
#pragma unroll
            for (int i = 0; i < 6; i++) wdst[tid + i * 256] = wsrc[tid + i * 256];
        }
        __syncthreads();

        const float* ipk = ins + ky * 68 + px0;
#pragma unroll 2
        for (int ci = 0; ci < 32; ci++) {
            const float* ip = ipk + ci * 204;
            float a0 = ip[0], a1 = ip[1], a2 = ip[2];
            float a3 = ip[3], a4 = ip[4], a5 = ip[5];
            ull d[6];
            d[0] = dup2(a0); d[1] = dup2(a1); d[2] = dup2(a2);
            d[3] = dup2(a3); d[4] = dup2(a4); d[5] = dup2(a5);
#pragma unroll
            for (int kx = 0; kx < 3; kx++) {
                ulonglong2 w = *(const ulonglong2*)&wsk[kx * 2048 + ci * 64 + co0];
                fma2(acc[0][0], d[kx + 0], w.x); fma2(acc[0][1], d[kx + 0], w.y);
                fma2(acc[1][0], d[kx + 1], w.x); fma2(acc[1][1], d[kx + 1], w.y);
                fma2(acc[2][0], d[kx + 2], w.x); fma2(acc[2][1], d[kx + 2], w.y);
                fma2(acc[3][0], d[kx + 3], w.x); fma2(acc[3][1], d[kx + 3], w.y);
            }
        }
    }

    float sc[4], mm[4], bbv[4];
#pragma unroll
    for (int j = 0; j < 4; j++) {
        int c = co0 + j;
        sc[j]  = __ldg(&bg[c]) * rsqrtf(__ldg(&bv[c]) + 1e-5f);
        mm[j]  = __ldg(&bm[c]);
        bbv[j] = __ldg(&bb[c]);
    }
    size_t pixbase = ((size_t)b * HH + y) * WW + x0 + px0;
#pragma unroll
    for (int i = 0; i < 4; i++) {
        float2 p0 = unpack2(acc[i][0]);
        float2 p1 = unpack2(acc[i][1]);
        float r0 = eluf((p0.x - mm[0]) * sc[0] + bbv[0]);
        float r1 = eluf((p0.y - mm[1]) * sc[1] + bbv[1]);
        float r2 = eluf((p1.x - mm[2]) * sc[2] + bbv[2]);
        float r3 = eluf((p1.y - mm[3]) * sc[3] + bbv[3]);
        uint2 o;
        o.x = h2pack(r0, r1);
        o.y = h2pack(r2, r3);
        *(uint2*)(g_h0 + (pixbase + i) * 64 + co0) = o;
    }
}

// ---------------- gemm1: hw = h0(fp16) @ gcn_w.T -> fp16 ----------------------
__global__ void __launch_bounds__(256)
k_gemm1(const float* __restrict__ Wm) {
    extern __shared__ float sm[];
    float* sA = sm;               // [256][65]
    float* sW = sm + 256 * 65;    // [64][68]

    int tid = threadIdx.x;
    size_t base = (size_t)blockIdx.x * 256;

    const uint2* src = (const uint2*)(g_h0 + base * 64);
#pragma unroll
    for (int i = 0; i < 16; i++) {
        int idx = tid + i * 256;
        int node = idx >> 4, c4 = idx & 15;
        uint2 v = src[idx];
        float2 f0 = __half22float2(*(__half2*)&v.x);
        float2 f1 = __half22float2(*(__half2*)&v.y);
        float* dst = &sA[node * 65 + c4 * 4];
        dst[0] = f0.x; dst[1] = f0.y; dst[2] = f1.x; dst[3] = f1.y;
    }
    const float4* w4 = (const float4*)Wm;
#pragma unroll
    for (int i = 0; i < 4; i++) {
        int idx = tid + i * 256;
        int co = idx >> 4, c4 = idx & 15;
        float4 v = w4[idx];
        sW[(c4 * 4 + 0) * 68 + co] = v.x;
        sW[(c4 * 4 + 1) * 68 + co] = v.y;
        sW[(c4 * 4 + 2) * 68 + co] = v.z;
        sW[(c4 * 4 + 3) * 68 + co] = v.w;
    }
    __syncthreads();

    int tx = tid & 7, ty = tid >> 3;
    int co0 = tx * 8, n0 = ty * 8;

    ull acc[8][4];
#pragma unroll
    for (int i = 0; i < 8; i++)
#pragma unroll
        for (int j = 0; j < 4; j++) acc[i][j] = 0ull;

    for (int ci = 0; ci < 64; ci++) {
        ulonglong2 w01 = *(const ulonglong2*)&sW[ci * 68 + co0];
        ulonglong2 w23 = *(const ulonglong2*)&sW[ci * 68 + co0 + 4];
        const float* ap = &sA[n0 * 65 + ci];
#pragma unroll
        for (int i = 0; i < 8; i++) {
            ull a = dup2(ap[i * 65]);
            fma2(acc[i][0], a, w01.x); fma2(acc[i][1], a, w01.y);
            fma2(acc[i][2], a, w23.x); fma2(acc[i][3], a, w23.y);
        }
    }
#pragma unroll
    for (int i = 0; i < 8; i++) {
        size_t node = base + n0 + i;
        float2 p0 = unpack2(acc[i][0]), p1 = unpack2(acc[i][1]);
        float2 p2 = unpack2(acc[i][2]), p3 = unpack2(acc[i][3]);
        uint4 o;
        o.x = h2pack(p0.x, p0.y); o.y = h2pack(p1.x, p1.y);
        o.z = h2pack(p2.x, p2.y); o.w = h2pack(p3.x, p3.y);
        *(uint4*)(g_hw + node * 64 + co0) = o;
    }
}

// ---------------- gcn gather (fp16 hw -> fp16 acc) ----------------
__global__ void __launch_bounds__(256)
k_gcn_gather() {
    int tid = threadIdx.x;
    int l = tid & 15;
    int node = blockIdx.x * 16 + (tid >> 4);
    int beg = g_off[node], end = g_off[node + 1];
    float dinvc = g_dinv[node];
    float s = 2.0f * dinvc * dinvc;
    uint2 hh = ((const uint2*)g_hw)[(size_t)node * 16 + l];
    float2 h0 = __half22float2(*(__half2*)&hh.x);
    float2 h1 = __half22float2(*(__half2*)&hh.y);
    float4 acc = make_float4(s * h0.x, s * h0.y, s * h1.x, s * h1.y);
    for (int p = beg; p < end; p++) {
        float4 m = g_meta[p];
        int r = __float_as_int(m.x);
        float coeff = g_dinv[r] * dinvc * m.z;
        uint2 vv = ((const uint2*)g_hw)[(size_t)r * 16 + l];
        float2 v0 = __half22float2(*(__half2*)&vv.x);
        float2 v1 = __half22float2(*(__half2*)&vv.y);
        acc.x += coeff * v0.x; acc.y += coeff * v0.y;
        acc.z += coeff * v1.x; acc.w += coeff * v1.y;
    }
    uint2 o;
    o.x = h2pack(acc.x, acc.y);
    o.y = h2pack(acc.z, acc.w);
    ((uint2*)g_acc)[(size_t)node * 16 + l] = o;
}

// ---------------- gemm4 (fp16 in/out except q) --------------------------------
__global__ void __launch_bounds__(256)
k_gemm4(const float* __restrict__ gb,
        const float* __restrict__ g1, const float* __restrict__ b1,
        const float* __restrict__ m1, const float* __restrict__ v1,
        const float* __restrict__ W0, const float* __restrict__ W1,
        const float* __restrict__ W2, const float* __restrict__ W3,
        const float* __restrict__ bb0, const float* __restrict__ bb1,
        const float* __restrict__ bb2, const float* __restrict__ bb3) {
    extern __shared__ float sm[];
    float* sA  = sm;                       // [256][65]
    float* sW2 = sm + 16640;               // [2][64*68]
    float* bs  = sm + 16640 + 8704;        // [4][64]
    float* pSc = bs + 256;
    float* pOf = pSc + 64;

    int tid = threadIdx.x;
    size_t base = (size_t)blockIdx.x * 256;
    const float* Wsrc[4] = {W0, W1, W2, W3};

    if (tid < 64) {
        float scv = __ldg(&g1[tid]) * rsqrtf(__ldg(&v1[tid]) + 1e-5f);
        pSc[tid] = scv;
        pOf[tid] = (__ldg(&gb[tid]) - __ldg(&m1[tid])) * scv + __ldg(&b1[tid]);
        bs[tid]       = __ldg(&bb0[tid]);
        bs[64 + tid]  = __ldg(&bb1[tid]);
        bs[128 + tid] = __ldg(&bb2[tid]);
        bs[192 + tid] = __ldg(&bb3[tid]);
    }
    __syncthreads();

    const uint2* src = (const uint2*)(g_acc + base * 64);
#pragma unroll
    for (int i = 0; i < 16; i++) {
        int idx = tid + i * 256;
        int node = idx >> 4, c4 = idx & 15;
        int c = c4 * 4;
        uint2 v = src[idx];
        float2 f0 = __half22float2(*(__half2*)&v.x);
        float2 f1 = __half22float2(*(__half2*)&v.y);
        float* dst = &sA[node * 65 + c];
        dst[0] = eluf(f0.x * pSc[c]     + pOf[c]);
        dst[1] = eluf(f0.y * pSc[c + 1] + pOf[c + 1]);
        dst[2] = eluf(f1.x * pSc[c + 2] + pOf[c + 2]);
        dst[3] = eluf(f1.y * pSc[c + 3] + pOf[c + 3]);
    }
    {
        const float4* w4 = (const float4*)W0;
        float* wb = sW2;
#pragma unroll
        for (int i = 0; i < 4; i++) {
            int idx = tid + i * 256;
            int co = idx >> 4, c4 = idx & 15;
            float4 v = w4[idx];
            wb[(c4 * 4 + 0) * 68 + co] = v.x;
            wb[(c4 * 4 + 1) * 68 + co] = v.y;
            wb[(c4 * 4 + 2) * 68 + co] = v.z;
            wb[(c4 * 4 + 3) * 68 + co] = v.w;
        }
    }
    __syncthreads();

    int tx = tid & 7, ty = tid >> 3;
    int co0 = tx * 8, n0 = ty * 8;

#pragma unroll
    for (int m = 0; m < 4; m++) {
        if (m < 3) {
            const float4* w4 = (const float4*)Wsrc[m + 1];
            float* wb = sW2 + ((m + 1) & 1) * 4352;
#pragma unroll
            for (int i = 0; i < 4; i++) {
                int idx = tid + i * 256;
                int co = idx >> 4, c4 = idx & 15;
                float4 v = w4[idx];
                wb[(c4 * 4 + 0) * 68 + co] = v.x;
                wb[(c4 * 4 + 1) * 68 + co] = v.y;
                wb[(c4 * 4 + 2) * 68 + co] = v.z;
                wb[(c4 * 4 + 3) * 68 + co] = v.w;
            }
        }
        const float* wb = sW2 + (m & 1) * 4352;
        ulonglong2 bi0 = *(const ulonglong2*)&bs[m * 64 + co0];
        ulonglong2 bi1 = *(const ulonglong2*)&bs[m * 64 + co0 + 4];
        ull acc[8][4];
#pragma unroll
        for (int i = 0; i < 8; i++) {
            acc[i][0] = bi0.x; acc[i][1] = bi0.y;
            acc[i][2] = bi1.x; acc[i][3] = bi1.y;
        }
        for (int ci = 0; ci < 64; ci++) {
            ulonglong2 w01 = *(const ulonglong2*)&wb[ci * 68 + co0];
            ulonglong2 w23 = *(const ulonglong2*)&wb[ci * 68 + co0 + 4];
            const float* ap = &sA[n0 * 65 + ci];
#pragma unroll
            for (int i = 0; i < 8; i++) {
                ull a = dup2(ap[i * 65]);
                fma2(acc[i][0], a, w01.x); fma2(acc[i][1], a, w01.y);
                fma2(acc[i][2], a, w23.x); fma2(acc[i][3], a, w23.y);
            }
        }
        if (m == 0) {
#pragma unroll
            for (int i = 0; i < 8; i++) {
                size_t node = base + n0 + i;
                float2 p0 = unpack2(acc[i][0]), p1 = unpack2(acc[i][1]);
                float2 p2 = unpack2(acc[i][2]), p3 = unpack2(acc[i][3]);
                *(float4*)(g_q + node * 64 + co0)     = make_float4(p0.x, p0.y, p1.x, p1.y);
                *(float4*)(g_q + node * 64 + co0 + 4) = make_float4(p2.x, p2.y, p3.x, p3.y);
            }
        } else {
            __half* out = (m == 1) ? g_kh : (m == 2) ? g_vh : g_acc2;
#pragma unroll
            for (int i = 0; i < 8; i++) {
                size_t node = base + n0 + i;
                float2 p0 = unpack2(acc[i][0]);
                float2 p1 = unpack2(acc[i][1]);
                float2 p2 = unpack2(acc[i][2]);
                float2 p3 = unpack2(acc[i][3]);
                uint4 o;
                o.x = h2pack(p0.x, p0.y); o.y = h2pack(p1.x, p1.y);
                o.z = h2pack(p2.x, p2.y); o.w = h2pack(p3.x, p3.y);
                *(uint4*)(out + node * 64 + co0) = o;
            }
        }
        __syncthreads();
    }
}

// ---------------- fused attention: single pass, fp16 k/v/skip ----------------
__global__ void __launch_bounds__(256)
k_attn(const float* __restrict__ we,
       const float* __restrict__ g1, const float* __restrict__ b1,
       const float* __restrict__ m1, const float* __restrict__ v1,
       const float* __restrict__ wl, const float* __restrict__ bl,
       float* __restrict__ out) {
    __shared__ float4 wesm4[32];
    int tid = threadIdx.x;
    if (tid < 32) wesm4[tid] = ((const float4*)we)[tid];
    __syncthreads();

    int l = tid & 15;
    int node = blockIdx.x * 16 + (tid >> 4);
    int beg = g_off[node], end = g_off[node + 1];
    unsigned mask = 0xFFFFu << (tid & 16);

    float4 q4 = ((const float4*)g_q)[(size_t)node * 16 + l];
    float4 wa = wesm4[l * 2];
    float4 wb = wesm4[l * 2 + 1];

    float qe0 = q4.x * wa.x + q4.y * wa.z + q4.z * wb.x + q4.w * wb.z;
    float qe1 = q4.x * wa.y + q4.y * wa.w + q4.z * wb.y + q4.w * wb.w;
    qe0 += __shfl_xor_sync(mask, qe0, 8); qe1 += __shfl_xor_sync(mask, qe1, 8);
    qe0 += __shfl_xor_sync(mask, qe0, 4); qe1 += __shfl_xor_sync(mask, qe1, 4);
    qe0 += __shfl_xor_sync(mask, qe0, 2); qe1 += __shfl_xor_sync(mask, qe1, 2);
    qe0 += __shfl_xor_sync(mask, qe0, 1); qe1 += __shfl_xor_sync(mask, qe1, 1);

    float d = 0.f;
    float4 acc = make_float4(0.f, 0.f, 0.f, 0.f);
    float ew0a = 0.f, ew1a = 0.f;
#pragma unroll 2
    for (int p = beg; p < end; p++) {
        float4 m = g_meta[p];
        int r = __float_as_int(m.x);
        uint2 kk = ((const uint2*)g_kh)[(size_t)r * 16 + l];
        float2 k0 = __half22float2(*(__half2*)&kk.x);
        float2 k1 = __half22float2(*(__half2*)&kk.y);
        float s = q4.x * k0.x + q4.y * k0.y + q4.z * k1.x + q4.w * k1.y;
        s += __shfl_xor_sync(mask, s, 8);
        s += __shfl_xor_sync(mask, s, 4);
        s += __shfl_xor_sync(mask, s, 2);
        s += __shfl_xor_sync(mask, s, 1);
        s = (s + qe0 * m.y + qe1 * m.z) * 0.125f;
        float f = expf(s);
        uint2 vv = ((const uint2*)g_vh)[(size_t)r * 16 + l];
        float2 v0 = __half22float2(*(__half2*)&vv.x);
        float2 v1 = __half22float2(*(__half2*)&vv.y);
        d += f;
        ew0a += f * m.y;
        ew1a += f * m.z;
        acc.x += f * v0.x; acc.y += f * v0.y;
        acc.z += f * v1.x; acc.w += f * v1.y;
    }
    float inv = d > 0.f ? 1.0f / d : 0.f;
    acc.x *= inv; acc.y *= inv; acc.z *= inv; acc.w *= inv;
    ew0a *= inv; ew1a *= inv;
    acc.x += wa.x * ew0a + wa.y * ew1a;
    acc.y += wa.z * ew0a + wa.w * ew1a;
    acc.z += wb.x * ew0a + wb.y * ew1a;
    acc.w += wb.z * ew0a + wb.w * ew1a;

    uint2 sk = ((const uint2*)g_acc2)[(size_t)node * 16 + l];
    float2 s0 = __half22float2(*(__half2*)&sk.x);
    float2 s1 = __half22float2(*(__half2*)&sk.y);
    int c0 = l * 4;
    float part = 0.f;
    float xv[4] = {acc.x + s0.x, acc.y + s0.y, acc.z + s1.x, acc.w + s1.y};
#pragma unroll
    for (int j = 0; j < 4; j++) {
        int c = c0 + j;
        float scv = __ldg(&g1[c]) * rsqrtf(__ldg(&v1[c]) + 1e-5f);
        float bnv = (xv[j] - __ldg(&m1[c])) * scv + __ldg(&b1[c]);
        part += bnv * __ldg(&wl[c]);
    }
    part += __shfl_xor_sync(mask, part, 8);
    part += __shfl_xor_sync(mask, part, 4);
    part += __shfl_xor_sync(mask, part, 2);
    part += __shfl_xor_sync(mask, part, 1);
    if (l == 0) out[node] = part + __ldg(&bl[0]);
}

// ---------------- host launcher (two-stream fork/join) ----------------------
extern "C" void kernel_launch(void* const* d_in, const int* in_sizes, int n_in,
                              void* d_out, int out_size) {
    (void)in_sizes; (void)n_in; (void)out_size;
    const float* x     = (const float*)d_in[0];
    const int*   ei    = (const int*)d_in[1];
    const float* ew    = (const float*)d_in[2];
    const float* cw    = (const float*)d_in[6];
    const float* bn2g  = (const float*)d_in[7];
    const float* bn2b  = (const float*)d_in[8];
    const float* bn2m  = (const float*)d_in[9];
    const float* bn2v  = (const float*)d_in[10];
    const float* gcnw  = (const float*)d_in[11];
    const float* gcnb  = (const float*)d_in[12];
    const float* bn1g  = (const float*)d_in[13];
    const float* bn1b  = (const float*)d_in[14];
    const float* bn1m  = (const float*)d_in[15];
    const float* bn1v  = (const float*)d_in[16];
    const float* wq    = (const float*)d_in[17];
    const float* bq    = (const float*)d_in[18];
    const float* wk    = (const float*)d_in[19];
    const float* bk    = (const float*)d_in[20];
    const float* wv    = (const float*)d_in[21];
    const float* bv    = (const float*)d_in[22];
    const float* we    = (const float*)d_in[23];
    const float* wsk   = (const float*)d_in[24];
    const float* bsk   = (const float*)d_in[25];
    const float* wl    = (const float*)d_in[26];
    const float* bl    = (const float*)d_in[27];

    const int gemm1_smem = (256 * 65 + 64 * 68) * 4;
    const int gemm4_smem = (16640 + 8704 + 256 + 128) * 4;

    static cudaStream_t s2 = nullptr;
    static cudaEvent_t evF = nullptr, evJ = nullptr;
    static bool attrSet = false;
    if (!attrSet) {
        cudaFuncSetAttribute(k_gemm1, cudaFuncAttributeMaxDynamicSharedMemorySize, gemm1_smem);
        cudaFuncSetAttribute(k_gemm4, cudaFuncAttributeMaxDynamicSharedMemorySize, gemm4_smem);
        cudaStreamCreateWithFlags(&s2, cudaStreamNonBlocking);
        cudaEventCreateWithFlags(&evF, cudaEventDisableTiming);
        cudaEventCreateWithFlags(&evJ, cudaEventDisableTiming);
        attrSet = true;
    }

    if (s2 && evF && evJ) {
        cudaEventRecord(evF, 0);
        cudaStreamWaitEvent(s2, evF, 0);
        k_init<<<NN / 256, 256, 0, s2>>>();
        k_cnt<<<EE / 256, 256, 0, s2>>>(ei);
        k_scan1<<<512, 256, 0, s2>>>();
        k_scan2<<<1, 512, 0, s2>>>();
        k_scan3<<<512, 256, 0, s2>>>();
        k_fill<<<EE / 256, 256, 0, s2>>>(ei, ew);
        k_degdinv<<<NN / 256, 256, 0, s2>>>();
        cudaEventRecord(evJ, s2);

        k_wprep<<<72, 256>>>(cw);
        k_conv<<<2048, 256>>>(x, bn2g, bn2b, bn2m, bn2v);
        k_gemm1<<<NN / 256, 256, gemm1_smem>>>(gcnw);

        cudaStreamWaitEvent(0, evJ, 0);
    } else {
        k_init<<<NN / 256, 256>>>();
        k_cnt<<<EE / 256, 256>>>(ei);
        k_scan1<<<512, 256>>>();
        k_scan2<<<1, 512>>>();
        k_scan3<<<512, 256>>>();
        k_fill<<<EE / 256, 256>>>(ei, ew);
        k_degdinv<<<NN / 256, 256>>>();
        k_wprep<<<72, 256>>>(cw);
        k_conv<<<2048, 256>>>(x, bn2g, bn2b, bn2m, bn2v);
        k_gemm1<<<NN / 256, 256, gemm1_smem>>>(gcnw);
    }

    k_gcn_gather<<<NN / 16, 256>>>();
    k_gemm4<<<NN / 256, 256, gemm4_smem>>>(gcnb, bn1g, bn1b, bn1m, bn1v,
                                           wq, wk, wv, wsk, bq, bk, bv, bsk);
    k_attn<<<NN / 16, 256>>>(we, bn1g, bn1b, bn1m, bn1v, wl, bl, (float*)d_out);
}